// round 7
// baseline (speedup 1.0000x reference)
#include <cuda_runtime.h>
#include <cstdint>
#include <cfloat>

// IBQ VQ: tf32 mma.sync screening + soundness certification + N-partitioned exact rescue.
//   d[b,n] = (sz[b]+se[n]) - 2*dot(z[b],e[n]);  idx=argmin (first index on ties)
// Ground truth (empirically == reference on all 32768 rows, R5): sequential-k fp32 FMA
// chain, d = fadd(fadd(sz,se), fmul(-2,p)). The MMA pass flags rows whose winner could
// differ from ground truth; flagged rows are recomputed exactly, partitioned over
// (row-group x code-slice) work items and merged via atomicMin on (d_bits, n) keys.

#define DIM      256
#define TM       128
#define TN       128
#define NSTAGE   3
#define THREADS  256
#define MAX_B    32768
#define MAX_NE   8192
#define THR      5e-7f
#define WINDOW   2.125f

__device__ float g_sz[MAX_B];
__device__ float g_se[MAX_NE];
__device__ float g_zhi[MAX_B * DIM];
__device__ float g_zlo[MAX_B * DIM];
__device__ float g_ehi[MAX_NE * DIM];
__device__ float g_elo[MAX_NE * DIM];
__device__ int   g_idx[MAX_B];
__device__ int   g_flag[MAX_B];
__device__ int   g_list[MAX_B];
__device__ int   g_cnt;
__device__ unsigned long long g_amin[MAX_B];

#define STG_BYTES   65536
#define OFF_SE      (3 * STG_BYTES)
#define OFF_RED_D   (OFF_SE + 512)
#define OFF_RED_N   (OFF_RED_D + 512)
#define OFF_RED_M   (OFF_RED_N + 512)
#define SMEM_REQ    (OFF_RED_M + 512)

__device__ __forceinline__ uint32_t smem_u32(const void* p) {
    uint32_t a;
    asm("{ .reg .u64 t; cvta.to.shared.u64 t, %1; cvt.u32.u64 %0, t; }" : "=r"(a) : "l"(p));
    return a;
}
__device__ __forceinline__ uint32_t f2tf32(float v) {
    uint32_t u; asm("cvt.rna.tf32.f32 %0, %1;" : "=r"(u) : "f"(v)); return u;
}
__device__ __forceinline__ void cp16(uint32_t s, const void* g) {
    asm volatile("cp.async.cg.shared.global [%0], [%1], 16;" :: "r"(s), "l"(g));
}
#define CP_COMMIT() asm volatile("cp.async.commit_group;" ::: "memory")
#define CP_WAIT2()  asm volatile("cp.async.wait_group 2;" ::: "memory")
#define CP_WAIT0()  asm volatile("cp.async.wait_group 0;" ::: "memory")

#define LDSM4(r, a) \
    asm volatile("ldmatrix.sync.aligned.m8n8.x4.shared.b16 {%0,%1,%2,%3}, [%4];" \
                 : "=r"((r)[0]), "=r"((r)[1]), "=r"((r)[2]), "=r"((r)[3]) : "r"(a))

#define MMA(d, a, b0, b1) \
    asm volatile("mma.sync.aligned.m16n8k8.row.col.f32.tf32.tf32.f32 " \
                 "{%0,%1,%2,%3}, {%4,%5,%6,%7}, {%8,%9}, {%0,%1,%2,%3};" \
                 : "+f"((d)[0]), "+f"((d)[1]), "+f"((d)[2]), "+f"((d)[3]) \
                 : "r"((a)[0]), "r"((a)[1]), "r"((a)[2]), "r"((a)[3]), "r"(b0), "r"(b1))

__device__ __forceinline__ uint32_t swz(int row, int g) {
    return (uint32_t)(row * 128 + ((g ^ (row & 7)) << 4));
}
__device__ __forceinline__ float ulp_of(float d) {
    return __uint_as_float(__float_as_uint(d) & 0xFF800000u) * 1.1920929e-7f;
}

// ---------------- prep kernels ----------------
__global__ void row_sumsq_kernel(const float* __restrict__ x, float* __restrict__ o, int rows) {
    int w = (int)((blockIdx.x * blockDim.x + threadIdx.x) >> 5);
    int lane = threadIdx.x & 31;
    if (w >= rows) return;
    const float4* r = (const float4*)(x + (size_t)w * DIM);
    float4 v0 = r[lane * 2];
    float4 v1 = r[lane * 2 + 1];
    float s = v0.x * v0.x;
    s += v0.y * v0.y; s += v0.z * v0.z; s += v0.w * v0.w;
    s += v1.x * v1.x; s += v1.y * v1.y; s += v1.z * v1.z; s += v1.w * v1.w;
#pragma unroll
    for (int off = 16; off; off >>= 1) s += __shfl_xor_sync(0xffffffffu, s, off);
    if (lane == 0) o[w] = s;
}

__global__ void split_tf32_kernel(const float* __restrict__ x, float* __restrict__ hi,
                                  float* __restrict__ lo, int n4) {
    int i = blockIdx.x * blockDim.x + threadIdx.x;
    if (i >= n4) return;
    float4 v = ((const float4*)x)[i];
    float4 h, l;
    h.x = __uint_as_float(f2tf32(v.x)); l.x = __uint_as_float(f2tf32(v.x - h.x));
    h.y = __uint_as_float(f2tf32(v.y)); l.y = __uint_as_float(f2tf32(v.y - h.y));
    h.z = __uint_as_float(f2tf32(v.z)); l.z = __uint_as_float(f2tf32(v.z - h.z));
    h.w = __uint_as_float(f2tf32(v.w)); l.w = __uint_as_float(f2tf32(v.w - h.w));
    ((float4*)hi)[i] = h;
    ((float4*)lo)[i] = l;
}

__global__ void init_kernel(int B) {
    int i = blockIdx.x * blockDim.x + threadIdx.x;
    if (i < B) g_amin[i] = ~0ull;
    if (i == 0) g_cnt = 0;
}

// ---------------- pass 1: tf32 MMA + certification ----------------
__global__ void __launch_bounds__(THREADS, 1)
vq_mma_kernel(const float* __restrict__ zhi, const float* __restrict__ zlo,
              const float* __restrict__ ehi, const float* __restrict__ elo,
              const float* __restrict__ sz, const float* __restrict__ se, int NE)
{
    extern __shared__ char sp[];
    const uint32_t sb = smem_u32(sp);

    const int tid  = threadIdx.x;
    const int lane = tid & 31;
    const int wid  = tid >> 5;
    const int wm   = (wid & 3) * 32;
    const int wn   = (wid >> 2) * 64;
    const int bbase = blockIdx.x * TM;
    const int NTILE = NE / TN;
    const int NCHK  = NTILE * 8;

    const int lrowA = lane & 15;
    const int gselA = lane >> 4;
    const int lrowB = (lane & 7) + ((lane >> 4) << 3);
    const int gselB = (lane >> 3) & 1;

    float d1[4] = {FLT_MAX, FLT_MAX, FLT_MAX, FLT_MAX};
    int   n1[4] = {0, 0, 0, 0};
    float dnm[4] = {FLT_MAX, FLT_MAX, FLT_MAX, FLT_MAX};

    float szr[4];
#pragma unroll
    for (int s = 0; s < 4; s++)
        szr[s] = __ldg(sz + bbase + wm + (s >> 1) * 16 + (s & 1) * 8 + (lane >> 2));

    float acc[2][8][4];
#pragma unroll
    for (int mt = 0; mt < 2; mt++)
#pragma unroll
        for (int nt = 0; nt < 8; nt++)
#pragma unroll
            for (int k = 0; k < 4; k++) acc[mt][nt][k] = 0.0f;

    auto issue_chunk = [&](int i, int stage) {
        int c = i & 7, t = i >> 3;
        uint32_t sA = sb + stage * STG_BYTES;
        const float* gAh = zhi + (size_t)bbase * DIM + c * 32;
        const float* gAl = zlo + (size_t)bbase * DIM + c * 32;
        const float* gBh = ehi + (size_t)t * TN * DIM + c * 32;
        const float* gBl = elo + (size_t)t * TN * DIM + c * 32;
#pragma unroll
        for (int it = 0; it < 4; it++) {
            int idx = tid + it * 256;
            int row = idx >> 3, g = idx & 7;
            uint32_t so = swz(row, g);
            size_t go = (size_t)row * DIM + g * 4;
            cp16(sA + so,         gAh + go);
            cp16(sA + 16384 + so, gAl + go);
            cp16(sA + 32768 + so, gBh + go);
            cp16(sA + 49152 + so, gBl + go);
        }
        CP_COMMIT();
    };

    issue_chunk(0, 0);
    issue_chunk(1, 1);
    issue_chunk(2, 2);

    float* sm_se = (float*)(sp + OFF_SE);

#pragma unroll 1
    for (int i = 0; i < NCHK; i++) {
        int stage = i % NSTAGE;
        CP_WAIT2();
        __syncthreads();

        if ((i & 7) == 0 && tid < 32)
            ((float4*)sm_se)[tid] = ((const float4*)(se + (i >> 3) * TN))[tid];

        uint32_t base = sb + stage * STG_BYTES;
#pragma unroll
        for (int ks = 0; ks < 4; ks++) {
            uint32_t ah[2][4], al[2][4], bh[4][4], bl[4][4];
#pragma unroll
            for (int mt = 0; mt < 2; mt++) {
                int row = wm + mt * 16 + lrowA;
                int g = ks * 2 + gselA;
                uint32_t ad = base + swz(row, g);
                LDSM4(ah[mt], ad);
                LDSM4(al[mt], ad + 16384);
            }
#pragma unroll
            for (int p = 0; p < 4; p++) {
                int row = wn + p * 16 + lrowB;
                int g = ks * 2 + gselB;
                uint32_t ad = base + 32768 + swz(row, g);
                LDSM4(bh[p], ad);
                LDSM4(bl[p], ad + 16384);
            }
#pragma unroll
            for (int mt = 0; mt < 2; mt++)
#pragma unroll
                for (int nt = 0; nt < 8; nt++) {
                    int p = nt >> 1, o = (nt & 1) * 2;
                    MMA(acc[mt][nt], ah[mt], bh[p][o], bh[p][o + 1]);
                    MMA(acc[mt][nt], al[mt], bh[p][o], bh[p][o + 1]);
                    MMA(acc[mt][nt], ah[mt], bl[p][o], bl[p][o + 1]);
                }
        }

        if ((i & 7) == 7) {
            int t = i >> 3;
#pragma unroll
            for (int mt = 0; mt < 2; mt++)
#pragma unroll
                for (int half = 0; half < 2; half++) {
                    int slot = mt * 2 + half;
                    float szv = szr[slot];
#pragma unroll
                    for (int nt = 0; nt < 8; nt++)
#pragma unroll
                        for (int j = 0; j < 2; j++) {
                            float p = acc[mt][nt][half * 2 + j];
                            int nl = wn + nt * 8 + (lane & 3) * 2 + j;
                            float tt = __fadd_rn(szv, sm_se[nl]);
                            float q  = __fmul_rn(-2.0f, p);
                            float d  = __fadd_rn(tt, q);
                            float zzv = __fadd_rn(d, -tt);   // exact (Fast2Sum)
                            float r   = __fadd_rn(q, -zzv);  // exact rounding residual
                            bool nm = fabsf(r) >= (0.5f * ulp_of(d) - THR);
                            if (nm && d < dnm[slot]) dnm[slot] = d;
                            int ng = t * TN + nl;
                            if (d < d1[slot]) { d1[slot] = d; n1[slot] = ng; }
                        }
                }
#pragma unroll
            for (int mt = 0; mt < 2; mt++)
#pragma unroll
                for (int nt = 0; nt < 8; nt++)
#pragma unroll
                    for (int k = 0; k < 4; k++) acc[mt][nt][k] = 0.0f;
        }

        __syncthreads();
        if (i + NSTAGE < NCHK) issue_chunk(i + NSTAGE, stage);
    }
    CP_WAIT0();

#pragma unroll
    for (int s = 0; s < 4; s++) {
#pragma unroll
        for (int off = 1; off <= 2; off <<= 1) {
            float od = __shfl_xor_sync(0xffffffffu, d1[s], off);
            int   on = __shfl_xor_sync(0xffffffffu, n1[s], off);
            float om = __shfl_xor_sync(0xffffffffu, dnm[s], off);
            if (od < d1[s] || (od == d1[s] && on < n1[s])) { d1[s] = od; n1[s] = on; }
            if (om < dnm[s]) dnm[s] = om;
        }
    }

    float* sd = (float*)(sp + OFF_RED_D);
    int*   sn = (int*)(sp + OFF_RED_N);
    float* sm = (float*)(sp + OFF_RED_M);
    if (wn == 0 && (lane & 3) == 0) {
#pragma unroll
        for (int s = 0; s < 4; s++) {
            int row = wm + (s >> 1) * 16 + (s & 1) * 8 + (lane >> 2);
            sd[row] = d1[s]; sn[row] = n1[s]; sm[row] = dnm[s];
        }
    }
    __syncthreads();
    if (wn != 0 && (lane & 3) == 0) {
#pragma unroll
        for (int s = 0; s < 4; s++) {
            int row = wm + (s >> 1) * 16 + (s & 1) * 8 + (lane >> 2);
            float od = sd[row]; int on = sn[row]; float om = sm[row];
            if (od < d1[s] || (od == d1[s] && on < n1[s])) { d1[s] = od; n1[s] = on; }
            if (om < dnm[s]) dnm[s] = om;
            g_idx[bbase + row] = n1[s];
            g_flag[bbase + row] = (dnm[s] <= d1[s] + WINDOW * ulp_of(d1[s])) ? 1 : 0;
        }
    }
}

// ---------------- compaction ----------------
__global__ void compact_kernel(int B) {
    int i = blockIdx.x * blockDim.x + threadIdx.x;
    if (i < B && g_flag[i]) {
        int p = atomicAdd(&g_cnt, 1);
        g_list[p] = i;
    }
}

// ---------------- rescue: exact ground-truth numerics, N-partitioned ----------------
// Work item = (group of 16 flagged rows) x (slice of 128 codes). Each (row, n) distance
// is computed with the R5-proven sequential-k fp32 FMA chain; partial winners merge via
// atomicMin on key = (float_bits(d) << 32) | n  (d > 0 so bits sort; ties -> min n).
#define RROWS 16

__global__ void __launch_bounds__(256, 1)
rescue2_kernel(const float* __restrict__ z, const float* __restrict__ emb,
               const float* __restrict__ sz, const float* __restrict__ se, int NE)
{
    __shared__ float smz[RROWS][DIM];

    const int tid = threadIdx.x;
    const int r = tid >> 4;       // row slot 0..15
    const int c = tid & 15;       // code group 0..15 (8 codes each)
    const int cnt = g_cnt;
    const int ngrp = (cnt + RROWS - 1) / RROWS;
    const int nslice = NE / 128;  // 64
    const int nitems = ngrp * nslice;

    for (int item = blockIdx.x; item < nitems; item += gridDim.x) {
        int grp = item / nslice;
        int slice = item - grp * nslice;

        int li = grp * RROWS + r;
        int grow = g_list[li < cnt ? li : cnt - 1];

        // load 16 z rows (16 threads x 16 floats each)
        {
            const float4* src = (const float4*)(z + (size_t)grow * DIM);
            float4* dst = (float4*)smz[r];
#pragma unroll
            for (int q = 0; q < 4; q++) dst[c * 4 + q] = src[c * 4 + q];
        }
        __syncthreads();

        float szv = __ldg(sz + grow);
        int nb = slice * 128 + c * 8;

        float acc[8] = {0, 0, 0, 0, 0, 0, 0, 0};
#pragma unroll 4
        for (int k4 = 0; k4 < DIM / 4; k4++) {
            float a0 = smz[r][k4 * 4 + 0];
            float a1 = smz[r][k4 * 4 + 1];
            float a2 = smz[r][k4 * 4 + 2];
            float a3 = smz[r][k4 * 4 + 3];
#pragma unroll
            for (int j = 0; j < 8; j++) {
                float4 b = __ldg((const float4*)(emb + (size_t)(nb + j) * DIM + k4 * 4));
                acc[j] = __fmaf_rn(a0, b.x, acc[j]);
                acc[j] = __fmaf_rn(a1, b.y, acc[j]);
                acc[j] = __fmaf_rn(a2, b.z, acc[j]);
                acc[j] = __fmaf_rn(a3, b.w, acc[j]);
            }
        }

        float bd = FLT_MAX; int bn = 0;
#pragma unroll
        for (int j = 0; j < 8; j++) {
            float tt = __fadd_rn(szv, __ldg(se + nb + j));
            float d = __fadd_rn(tt, __fmul_rn(-2.0f, acc[j]));
            int n = nb + j;
            if (d < bd || (d == bd && n < bn)) { bd = d; bn = n; }
        }

        if (li < cnt) {
            unsigned long long key =
                ((unsigned long long)__float_as_uint(bd) << 32) | (unsigned)bn;
            atomicMin(&g_amin[grow], key);
        }
        __syncthreads();
    }
}

// ---------------- output gather ----------------
__global__ void gather_kernel(const float* __restrict__ emb, float* __restrict__ outp,
                              int B, int mode, long long idx_off)
{
    int w = (int)((blockIdx.x * blockDim.x + threadIdx.x) >> 5);
    int lane = threadIdx.x & 31;
    if (w >= B) return;
    int idx = g_flag[w] ? (int)(unsigned)(g_amin[w] & 0xFFFFFFFFull) : g_idx[w];
    if (mode & 1) {
        const float4* src = (const float4*)(emb + (size_t)idx * DIM);
        float4* dst = (float4*)(outp + (size_t)w * DIM);
        dst[lane] = src[lane];
        dst[lane + 32] = src[lane + 32];
    }
    if ((mode & 2) && lane == 0) outp[idx_off + w] = (float)idx;
}

extern "C" void kernel_launch(void* const* d_in, const int* in_sizes, int n_in,
                              void* d_out, int out_size) {
    const float* z   = (const float*)d_in[0];
    const float* emb = (const float*)d_in[1];
    float* outp = (float*)d_out;

    int B  = in_sizes[0] / DIM;
    int NE = in_sizes[1] / DIM;

    float *sz_p, *se_p, *zhi_p, *zlo_p, *ehi_p, *elo_p;
    cudaGetSymbolAddress((void**)&sz_p,  g_sz);
    cudaGetSymbolAddress((void**)&se_p,  g_se);
    cudaGetSymbolAddress((void**)&zhi_p, g_zhi);
    cudaGetSymbolAddress((void**)&zlo_p, g_zlo);
    cudaGetSymbolAddress((void**)&ehi_p, g_ehi);
    cudaGetSymbolAddress((void**)&elo_p, g_elo);

    row_sumsq_kernel<<<(B + 7) / 8, 256>>>(z, sz_p, B);
    row_sumsq_kernel<<<(NE + 7) / 8, 256>>>(emb, se_p, NE);
    int nz4 = B * DIM / 4, ne4 = NE * DIM / 4;
    split_tf32_kernel<<<(nz4 + 255) / 256, 256>>>(z, zhi_p, zlo_p, nz4);
    split_tf32_kernel<<<(ne4 + 255) / 256, 256>>>(emb, ehi_p, elo_p, ne4);

    init_kernel<<<(B + 255) / 256, 256>>>(B);

    cudaFuncSetAttribute(vq_mma_kernel, cudaFuncAttributeMaxDynamicSharedMemorySize, SMEM_REQ);
    vq_mma_kernel<<<B / TM, THREADS, SMEM_REQ>>>(zhi_p, zlo_p, ehi_p, elo_p, sz_p, se_p, NE);

    compact_kernel<<<(B + 255) / 256, 256>>>(B);

    rescue2_kernel<<<2048, 256>>>(z, emb, sz_p, se_p, NE);

    long long zq_elems = (long long)B * DIM;
    int mode; long long idx_off;
    if ((long long)out_size >= zq_elems + B) { mode = 3; idx_off = zq_elems; }
    else if ((long long)out_size >= zq_elems) { mode = 1; idx_off = 0; }
    else { mode = 2; idx_off = 0; }

    gather_kernel<<<(B * 32 + 255) / 256, 256>>>(emb, outp, B, mode, idx_off);
}

// round 8
// speedup vs baseline: 2.2709x; 2.2709x over previous
#include <cuda_runtime.h>
#include <cstdint>
#include <cfloat>

// IBQ VQ: tf32 mma.sync screening + soundness certification + n-partitioned tiled rescue.
//   d[b,n] = (sz[b]+se[n]) - 2*dot(z[b],e[n]);  idx=argmin (first index on ties)
// Ground truth (empirically == reference on all 32768 rows, R5/R6): sequential-k fp32 FMA
// chain, d = fadd(fadd(sz,se), fmul(-2,p)). The MMA pass flags rows whose winner could
// differ from ground truth; flagged rows are recomputed exactly with the R6 tiled-GEMM
// rescue, partitioned (row-tile x 1024-code slice) and merged via atomicMin keys.

#define DIM      256
#define TM       128
#define TN       128
#define NSTAGE   3
#define THREADS  256
#define MAX_B    32768
#define MAX_NE   8192
#define THR      5e-7f
#define WINDOW   1.125f

__device__ float g_sz[MAX_B];
__device__ float g_se[MAX_NE];
__device__ float g_zhi[MAX_B * DIM];
__device__ float g_zlo[MAX_B * DIM];
__device__ float g_ehi[MAX_NE * DIM];
__device__ float g_elo[MAX_NE * DIM];
__device__ int   g_idx[MAX_B];
__device__ int   g_flag[MAX_B];
__device__ int   g_list[MAX_B];
__device__ int   g_cnt;
__device__ unsigned long long g_amin[MAX_B];

#define STG_BYTES   65536
#define OFF_SE      (3 * STG_BYTES)
#define OFF_RED_D   (OFF_SE + 512)
#define OFF_RED_N   (OFF_RED_D + 512)
#define OFF_RED_M   (OFF_RED_N + 512)
#define SMEM_REQ    (OFF_RED_M + 512)

__device__ __forceinline__ uint32_t smem_u32(const void* p) {
    uint32_t a;
    asm("{ .reg .u64 t; cvta.to.shared.u64 t, %1; cvt.u32.u64 %0, t; }" : "=r"(a) : "l"(p));
    return a;
}
__device__ __forceinline__ uint32_t f2tf32(float v) {
    uint32_t u; asm("cvt.rna.tf32.f32 %0, %1;" : "=r"(u) : "f"(v)); return u;
}
__device__ __forceinline__ void cp16(uint32_t s, const void* g) {
    asm volatile("cp.async.cg.shared.global [%0], [%1], 16;" :: "r"(s), "l"(g));
}
#define CP_COMMIT() asm volatile("cp.async.commit_group;" ::: "memory")
#define CP_WAIT2()  asm volatile("cp.async.wait_group 2;" ::: "memory")
#define CP_WAIT0()  asm volatile("cp.async.wait_group 0;" ::: "memory")

#define LDSM4(r, a) \
    asm volatile("ldmatrix.sync.aligned.m8n8.x4.shared.b16 {%0,%1,%2,%3}, [%4];" \
                 : "=r"((r)[0]), "=r"((r)[1]), "=r"((r)[2]), "=r"((r)[3]) : "r"(a))

#define MMA(d, a, b0, b1) \
    asm volatile("mma.sync.aligned.m16n8k8.row.col.f32.tf32.tf32.f32 " \
                 "{%0,%1,%2,%3}, {%4,%5,%6,%7}, {%8,%9}, {%0,%1,%2,%3};" \
                 : "+f"((d)[0]), "+f"((d)[1]), "+f"((d)[2]), "+f"((d)[3]) \
                 : "r"((a)[0]), "r"((a)[1]), "r"((a)[2]), "r"((a)[3]), "r"(b0), "r"(b1))

__device__ __forceinline__ uint32_t swz(int row, int g) {
    return (uint32_t)(row * 128 + ((g ^ (row & 7)) << 4));
}
__device__ __forceinline__ float ulp_of(float d) {
    return __uint_as_float(__float_as_uint(d) & 0xFF800000u) * 1.1920929e-7f;
}

typedef unsigned long long ull;
#define PACK2(d, x, y) \
    asm("mov.b64 %0, {%1, %2};" : "=l"(d) : "r"(__float_as_uint(x)), "r"(__float_as_uint(y)))
#define FMA2(acc, a, b) \
    asm("fma.rn.f32x2 %0, %1, %2, %3;" : "=l"(acc) : "l"(a), "l"(b), "l"(acc))
#define UNPACK2(x, y, d) \
    asm("mov.b64 {%0, %1}, %2;" : "=r"(x), "=r"(y) : "l"(d))

// ---------------- prep kernels ----------------
__global__ void row_sumsq_kernel(const float* __restrict__ x, float* __restrict__ o, int rows) {
    int w = (int)((blockIdx.x * blockDim.x + threadIdx.x) >> 5);
    int lane = threadIdx.x & 31;
    if (w >= rows) return;
    const float4* r = (const float4*)(x + (size_t)w * DIM);
    float4 v0 = r[lane * 2];
    float4 v1 = r[lane * 2 + 1];
    float s = v0.x * v0.x;
    s += v0.y * v0.y; s += v0.z * v0.z; s += v0.w * v0.w;
    s += v1.x * v1.x; s += v1.y * v1.y; s += v1.z * v1.z; s += v1.w * v1.w;
#pragma unroll
    for (int off = 16; off; off >>= 1) s += __shfl_xor_sync(0xffffffffu, s, off);
    if (lane == 0) o[w] = s;
}

__global__ void split_tf32_kernel(const float* __restrict__ x, float* __restrict__ hi,
                                  float* __restrict__ lo, int n4) {
    int i = blockIdx.x * blockDim.x + threadIdx.x;
    if (i >= n4) return;
    float4 v = ((const float4*)x)[i];
    float4 h, l;
    h.x = __uint_as_float(f2tf32(v.x)); l.x = __uint_as_float(f2tf32(v.x - h.x));
    h.y = __uint_as_float(f2tf32(v.y)); l.y = __uint_as_float(f2tf32(v.y - h.y));
    h.z = __uint_as_float(f2tf32(v.z)); l.z = __uint_as_float(f2tf32(v.z - h.z));
    h.w = __uint_as_float(f2tf32(v.w)); l.w = __uint_as_float(f2tf32(v.w - h.w));
    ((float4*)hi)[i] = h;
    ((float4*)lo)[i] = l;
}

__global__ void init_kernel(int B) {
    int i = blockIdx.x * blockDim.x + threadIdx.x;
    if (i < B) g_amin[i] = ~0ull;
    if (i == 0) g_cnt = 0;
}

// ---------------- pass 1: tf32 MMA + certification ----------------
__global__ void __launch_bounds__(THREADS, 1)
vq_mma_kernel(const float* __restrict__ zhi, const float* __restrict__ zlo,
              const float* __restrict__ ehi, const float* __restrict__ elo,
              const float* __restrict__ sz, const float* __restrict__ se, int NE)
{
    extern __shared__ char sp[];
    const uint32_t sb = smem_u32(sp);

    const int tid  = threadIdx.x;
    const int lane = tid & 31;
    const int wid  = tid >> 5;
    const int wm   = (wid & 3) * 32;
    const int wn   = (wid >> 2) * 64;
    const int bbase = blockIdx.x * TM;
    const int NTILE = NE / TN;
    const int NCHK  = NTILE * 8;

    const int lrowA = lane & 15;
    const int gselA = lane >> 4;
    const int lrowB = (lane & 7) + ((lane >> 4) << 3);
    const int gselB = (lane >> 3) & 1;

    float d1[4] = {FLT_MAX, FLT_MAX, FLT_MAX, FLT_MAX};
    int   n1[4] = {0, 0, 0, 0};
    float dnm[4] = {FLT_MAX, FLT_MAX, FLT_MAX, FLT_MAX};

    float szr[4];
#pragma unroll
    for (int s = 0; s < 4; s++)
        szr[s] = __ldg(sz + bbase + wm + (s >> 1) * 16 + (s & 1) * 8 + (lane >> 2));

    float acc[2][8][4];
#pragma unroll
    for (int mt = 0; mt < 2; mt++)
#pragma unroll
        for (int nt = 0; nt < 8; nt++)
#pragma unroll
            for (int k = 0; k < 4; k++) acc[mt][nt][k] = 0.0f;

    auto issue_chunk = [&](int i, int stage) {
        int c = i & 7, t = i >> 3;
        uint32_t sA = sb + stage * STG_BYTES;
        const float* gAh = zhi + (size_t)bbase * DIM + c * 32;
        const float* gAl = zlo + (size_t)bbase * DIM + c * 32;
        const float* gBh = ehi + (size_t)t * TN * DIM + c * 32;
        const float* gBl = elo + (size_t)t * TN * DIM + c * 32;
#pragma unroll
        for (int it = 0; it < 4; it++) {
            int idx = tid + it * 256;
            int row = idx >> 3, g = idx & 7;
            uint32_t so = swz(row, g);
            size_t go = (size_t)row * DIM + g * 4;
            cp16(sA + so,         gAh + go);
            cp16(sA + 16384 + so, gAl + go);
            cp16(sA + 32768 + so, gBh + go);
            cp16(sA + 49152 + so, gBl + go);
        }
        CP_COMMIT();
    };

    issue_chunk(0, 0);
    issue_chunk(1, 1);
    issue_chunk(2, 2);

    float* sm_se = (float*)(sp + OFF_SE);

#pragma unroll 1
    for (int i = 0; i < NCHK; i++) {
        int stage = i % NSTAGE;
        CP_WAIT2();
        __syncthreads();

        if ((i & 7) == 0 && tid < 32)
            ((float4*)sm_se)[tid] = ((const float4*)(se + (i >> 3) * TN))[tid];

        uint32_t base = sb + stage * STG_BYTES;
#pragma unroll
        for (int ks = 0; ks < 4; ks++) {
            uint32_t ah[2][4], al[2][4], bh[4][4], bl[4][4];
#pragma unroll
            for (int mt = 0; mt < 2; mt++) {
                int row = wm + mt * 16 + lrowA;
                int g = ks * 2 + gselA;
                uint32_t ad = base + swz(row, g);
                LDSM4(ah[mt], ad);
                LDSM4(al[mt], ad + 16384);
            }
#pragma unroll
            for (int p = 0; p < 4; p++) {
                int row = wn + p * 16 + lrowB;
                int g = ks * 2 + gselB;
                uint32_t ad = base + 32768 + swz(row, g);
                LDSM4(bh[p], ad);
                LDSM4(bl[p], ad + 16384);
            }
#pragma unroll
            for (int mt = 0; mt < 2; mt++)
#pragma unroll
                for (int nt = 0; nt < 8; nt++) {
                    int p = nt >> 1, o = (nt & 1) * 2;
                    MMA(acc[mt][nt], ah[mt], bh[p][o], bh[p][o + 1]);
                    MMA(acc[mt][nt], al[mt], bh[p][o], bh[p][o + 1]);
                    MMA(acc[mt][nt], ah[mt], bl[p][o], bl[p][o + 1]);
                }
        }

        if ((i & 7) == 7) {
            int t = i >> 3;
#pragma unroll
            for (int mt = 0; mt < 2; mt++)
#pragma unroll
                for (int half = 0; half < 2; half++) {
                    int slot = mt * 2 + half;
                    float szv = szr[slot];
#pragma unroll
                    for (int nt = 0; nt < 8; nt++)
#pragma unroll
                        for (int j = 0; j < 2; j++) {
                            float p = acc[mt][nt][half * 2 + j];
                            int nl = wn + nt * 8 + (lane & 3) * 2 + j;
                            float tt = __fadd_rn(szv, sm_se[nl]);
                            float q  = __fmul_rn(-2.0f, p);
                            float d  = __fadd_rn(tt, q);
                            float zzv = __fadd_rn(d, -tt);   // exact (Fast2Sum)
                            float r   = __fadd_rn(q, -zzv);  // exact rounding residual
                            bool nm = fabsf(r) >= (0.5f * ulp_of(d) - THR);
                            if (nm && d < dnm[slot]) dnm[slot] = d;
                            int ng = t * TN + nl;
                            if (d < d1[slot]) { d1[slot] = d; n1[slot] = ng; }
                        }
                }
#pragma unroll
            for (int mt = 0; mt < 2; mt++)
#pragma unroll
                for (int nt = 0; nt < 8; nt++)
#pragma unroll
                    for (int k = 0; k < 4; k++) acc[mt][nt][k] = 0.0f;
        }

        __syncthreads();
        if (i + NSTAGE < NCHK) issue_chunk(i + NSTAGE, stage);
    }
    CP_WAIT0();

#pragma unroll
    for (int s = 0; s < 4; s++) {
#pragma unroll
        for (int off = 1; off <= 2; off <<= 1) {
            float od = __shfl_xor_sync(0xffffffffu, d1[s], off);
            int   on = __shfl_xor_sync(0xffffffffu, n1[s], off);
            float om = __shfl_xor_sync(0xffffffffu, dnm[s], off);
            if (od < d1[s] || (od == d1[s] && on < n1[s])) { d1[s] = od; n1[s] = on; }
            if (om < dnm[s]) dnm[s] = om;
        }
    }

    float* sd = (float*)(sp + OFF_RED_D);
    int*   sn = (int*)(sp + OFF_RED_N);
    float* sm = (float*)(sp + OFF_RED_M);
    if (wn == 0 && (lane & 3) == 0) {
#pragma unroll
        for (int s = 0; s < 4; s++) {
            int row = wm + (s >> 1) * 16 + (s & 1) * 8 + (lane >> 2);
            sd[row] = d1[s]; sn[row] = n1[s]; sm[row] = dnm[s];
        }
    }
    __syncthreads();
    if (wn != 0 && (lane & 3) == 0) {
#pragma unroll
        for (int s = 0; s < 4; s++) {
            int row = wm + (s >> 1) * 16 + (s & 1) * 8 + (lane >> 2);
            float od = sd[row]; int on = sn[row]; float om = sm[row];
            if (od < d1[s] || (od == d1[s] && on < n1[s])) { d1[s] = od; n1[s] = on; }
            if (om < dnm[s]) dnm[s] = om;
            g_idx[bbase + row] = n1[s];
            g_flag[bbase + row] = (dnm[s] <= d1[s] + WINDOW * ulp_of(d1[s])) ? 1 : 0;
        }
    }
}

// ---------------- compaction ----------------
__global__ void compact_kernel(int B) {
    int i = blockIdx.x * blockDim.x + threadIdx.x;
    if (i < B && g_flag[i]) {
        int p = atomicAdd(&g_cnt, 1);
        g_list[p] = i;
    }
}

// ---------------- rescue: R6 tiled structure, n-partitioned ----------------
// Work item = (128-row flagged group) x (1024-code slice).  Per-(row,n) distance uses the
// proven sequential-k fp32 FMA2 chain; slice winners merge via atomicMin on
// key = (float_bits(d) << 32) | n  (d > 0 so bits sort; ties -> min n).
#define RBM 128
#define RBN 128
#define RBK 32
#define SLICE_N 1024

__global__ void __launch_bounds__(256, 1)
rescue3_kernel(const float* __restrict__ z, const float* __restrict__ emb,
               const float* __restrict__ sz, const float* __restrict__ se, int NE)
{
    extern __shared__ float smem[];
    float* sm_z  = smem;                 // [DIM][RBM] transposed
    float* sm_e  = smem + DIM * RBM;     // [RBK][RBN]
    float* run_d = sm_e + RBK * RBN;     // [RBM]
    int*   run_n = (int*)(run_d + RBM);  // [RBM]

    const int tid = threadIdx.x;
    const int tx = tid & 15;
    const int ty = tid >> 4;
    const int cnt = g_cnt;
    const int ngrp = (cnt + RBM - 1) / RBM;
    const int nslice = NE / SLICE_N;     // 8
    const int nitems = ngrp * nslice;

    for (int item = blockIdx.x; item < nitems; item += gridDim.x) {
        const int grp = item / nslice;
        const int slice = item - grp * nslice;
        const int n0 = slice * SLICE_N;

        // transposed z-tile load via indirection
        {
            int r = tid >> 1, half = tid & 1;
            int li = grp * RBM + r;
            int grow = g_list[li < cnt ? li : cnt - 1];
            const float4* src = (const float4*)(z + (size_t)grow * DIM + half * 128);
#pragma unroll
            for (int qq = 0; qq < 32; qq++) {
                float4 v = src[qq];
                int k = half * 128 + qq * 4;
                sm_z[(k + 0) * RBM + r] = v.x;
                sm_z[(k + 1) * RBM + r] = v.y;
                sm_z[(k + 2) * RBM + r] = v.z;
                sm_z[(k + 3) * RBM + r] = v.w;
            }
        }
        if (tid < RBM) { run_d[tid] = FLT_MAX; run_n[tid] = 0; }

        float szr[8];
#pragma unroll
        for (int i = 0; i < 8; i++) {
            int li = grp * RBM + ty * 8 + i;
            szr[i] = __ldg(sz + g_list[li < cnt ? li : cnt - 1]);
        }
        __syncthreads();

        const int ec = tid >> 1;
        const int ekh = (tid & 1) * 16;

#pragma unroll 1
        for (int nbase = n0; nbase < n0 + SLICE_N; nbase += RBN) {
            ull acc2[8][4];
#pragma unroll
            for (int i = 0; i < 8; i++)
#pragma unroll
                for (int j = 0; j < 4; j++) acc2[i][j] = 0ull;

            float4 pf0, pf1, pf2, pf3;
            {
                const float4* src = (const float4*)(emb + (size_t)(nbase + ec) * DIM + ekh);
                pf0 = src[0]; pf1 = src[1]; pf2 = src[2]; pf3 = src[3];
            }

#pragma unroll 1
            for (int s = 0; s < DIM / RBK; s++) {
                __syncthreads();
                {
                    float* dst = sm_e + ec;
                    dst[(ekh + 0)  * RBN] = pf0.x; dst[(ekh + 1)  * RBN] = pf0.y;
                    dst[(ekh + 2)  * RBN] = pf0.z; dst[(ekh + 3)  * RBN] = pf0.w;
                    dst[(ekh + 4)  * RBN] = pf1.x; dst[(ekh + 5)  * RBN] = pf1.y;
                    dst[(ekh + 6)  * RBN] = pf1.z; dst[(ekh + 7)  * RBN] = pf1.w;
                    dst[(ekh + 8)  * RBN] = pf2.x; dst[(ekh + 9)  * RBN] = pf2.y;
                    dst[(ekh + 10) * RBN] = pf2.z; dst[(ekh + 11) * RBN] = pf2.w;
                    dst[(ekh + 12) * RBN] = pf3.x; dst[(ekh + 13) * RBN] = pf3.y;
                    dst[(ekh + 14) * RBN] = pf3.z; dst[(ekh + 15) * RBN] = pf3.w;
                }
                __syncthreads();
                if (s + 1 < DIM / RBK) {
                    const float4* src = (const float4*)(emb + (size_t)(nbase + ec) * DIM
                                                        + (s + 1) * RBK + ekh);
                    pf0 = src[0]; pf1 = src[1]; pf2 = src[2]; pf3 = src[3];
                }
                const float* zs = sm_z + (s * RBK) * RBM + ty * 8;
                const float* es = sm_e + tx * 8;
#pragma unroll 8
                for (int kk = 0; kk < RBK; kk++) {
                    float4 a0 = *(const float4*)(zs + kk * RBM);
                    float4 a1 = *(const float4*)(zs + kk * RBM + 4);
                    float4 b0 = *(const float4*)(es + kk * RBN);
                    float4 b1 = *(const float4*)(es + kk * RBN + 4);
                    ull bb0, bb1, bb2, bb3;
                    PACK2(bb0, b0.x, b0.y); PACK2(bb1, b0.z, b0.w);
                    PACK2(bb2, b1.x, b1.y); PACK2(bb3, b1.z, b1.w);
                    float av[8] = {a0.x, a0.y, a0.z, a0.w, a1.x, a1.y, a1.z, a1.w};
#pragma unroll
                    for (int i = 0; i < 8; i++) {
                        ull aa; PACK2(aa, av[i], av[i]);
                        FMA2(acc2[i][0], aa, bb0);
                        FMA2(acc2[i][1], aa, bb1);
                        FMA2(acc2[i][2], aa, bb2);
                        FMA2(acc2[i][3], aa, bb3);
                    }
                }
            }

            float4 se0 = *(const float4*)(se + nbase + tx * 8);
            float4 se1 = *(const float4*)(se + nbase + tx * 8 + 4);
            float sen[8] = {se0.x, se0.y, se0.z, se0.w, se1.x, se1.y, se1.z, se1.w};
#pragma unroll
            for (int i = 0; i < 8; i++) {
                float bdv = FLT_MAX; int bnv = 0;
#pragma unroll
                for (int j2 = 0; j2 < 4; j2++) {
                    unsigned plo_u, phi_u;
                    UNPACK2(plo_u, phi_u, acc2[i][j2]);
                    float plo = __uint_as_float(plo_u);
                    float phi = __uint_as_float(phi_u);
                    float t0 = __fadd_rn(szr[i], sen[2 * j2]);
                    float t1 = __fadd_rn(szr[i], sen[2 * j2 + 1]);
                    float dd0 = __fadd_rn(t0, __fmul_rn(-2.0f, plo));
                    float dd1 = __fadd_rn(t1, __fmul_rn(-2.0f, phi));
                    if (dd0 < bdv) { bdv = dd0; bnv = nbase + tx * 8 + 2 * j2; }
                    if (dd1 < bdv) { bdv = dd1; bnv = nbase + tx * 8 + 2 * j2 + 1; }
                }
#pragma unroll
                for (int off = 8; off; off >>= 1) {
                    float od = __shfl_down_sync(0xffffffffu, bdv, off, 16);
                    int   on = __shfl_down_sync(0xffffffffu, bnv, off, 16);
                    if (od < bdv || (od == bdv && on < bnv)) { bdv = od; bnv = on; }
                }
                if (tx == 0) {
                    int rr = ty * 8 + i;
                    if (bdv < run_d[rr]) { run_d[rr] = bdv; run_n[rr] = bnv; }
                }
            }
        }

        __syncthreads();
        if (tid < RBM) {
            int li = grp * RBM + tid;
            if (li < cnt) {
                unsigned long long key =
                    ((unsigned long long)__float_as_uint(run_d[tid]) << 32)
                    | (unsigned)run_n[tid];
                atomicMin(&g_amin[g_list[li]], key);
            }
        }
        __syncthreads();
    }
}

// ---------------- output gather ----------------
__global__ void gather_kernel(const float* __restrict__ emb, float* __restrict__ outp,
                              int B, int mode, long long idx_off)
{
    int w = (int)((blockIdx.x * blockDim.x + threadIdx.x) >> 5);
    int lane = threadIdx.x & 31;
    if (w >= B) return;
    int idx = g_flag[w] ? (int)(unsigned)(g_amin[w] & 0xFFFFFFFFull) : g_idx[w];
    if (mode & 1) {
        const float4* src = (const float4*)(emb + (size_t)idx * DIM);
        float4* dst = (float4*)(outp + (size_t)w * DIM);
        dst[lane] = src[lane];
        dst[lane + 32] = src[lane + 32];
    }
    if ((mode & 2) && lane == 0) outp[idx_off + w] = (float)idx;
}

extern "C" void kernel_launch(void* const* d_in, const int* in_sizes, int n_in,
                              void* d_out, int out_size) {
    const float* z   = (const float*)d_in[0];
    const float* emb = (const float*)d_in[1];
    float* outp = (float*)d_out;

    int B  = in_sizes[0] / DIM;
    int NE = in_sizes[1] / DIM;

    float *sz_p, *se_p, *zhi_p, *zlo_p, *ehi_p, *elo_p;
    cudaGetSymbolAddress((void**)&sz_p,  g_sz);
    cudaGetSymbolAddress((void**)&se_p,  g_se);
    cudaGetSymbolAddress((void**)&zhi_p, g_zhi);
    cudaGetSymbolAddress((void**)&zlo_p, g_zlo);
    cudaGetSymbolAddress((void**)&ehi_p, g_ehi);
    cudaGetSymbolAddress((void**)&elo_p, g_elo);

    row_sumsq_kernel<<<(B + 7) / 8, 256>>>(z, sz_p, B);
    row_sumsq_kernel<<<(NE + 7) / 8, 256>>>(emb, se_p, NE);
    int nz4 = B * DIM / 4, ne4 = NE * DIM / 4;
    split_tf32_kernel<<<(nz4 + 255) / 256, 256>>>(z, zhi_p, zlo_p, nz4);
    split_tf32_kernel<<<(ne4 + 255) / 256, 256>>>(emb, ehi_p, elo_p, ne4);

    init_kernel<<<(B + 255) / 256, 256>>>(B);

    cudaFuncSetAttribute(vq_mma_kernel, cudaFuncAttributeMaxDynamicSharedMemorySize, SMEM_REQ);
    vq_mma_kernel<<<B / TM, THREADS, SMEM_REQ>>>(zhi_p, zlo_p, ehi_p, elo_p, sz_p, se_p, NE);

    compact_kernel<<<(B + 255) / 256, 256>>>(B);

    size_t rs_smem = (size_t)(DIM * RBM + RBK * RBN + RBM) * sizeof(float) + RBM * sizeof(int);
    cudaFuncSetAttribute(rescue3_kernel, cudaFuncAttributeMaxDynamicSharedMemorySize, (int)rs_smem);
    rescue3_kernel<<<512, 256, rs_smem>>>(z, emb, sz_p, se_p, NE);

    long long zq_elems = (long long)B * DIM;
    int mode; long long idx_off;
    if ((long long)out_size >= zq_elems + B) { mode = 3; idx_off = zq_elems; }
    else if ((long long)out_size >= zq_elems) { mode = 1; idx_off = 0; }
    else { mode = 2; idx_off = 0; }

    gather_kernel<<<(B * 32 + 255) / 256, 256>>>(emb, outp, B, mode, idx_off);
}

// round 9
// speedup vs baseline: 3.7755x; 1.6626x over previous
#include <cuda_runtime.h>
#include <cuda_bf16.h>
#include <cstdint>
#include <cfloat>

// IBQ VQ: bf16 3-term mma.sync screening (persistent-A) + soundness certification +
// n-partitioned exact-fp32 tiled rescue (R8 machinery, unchanged).
//   d[b,n] = (sz[b]+se[n]) - 2*dot(z[b],e[n]);  idx=argmin (first index on ties)
// Ground truth (empirically == reference, R5/R6/R8): sequential-k fp32 FMA chain,
// d = fadd(fadd(sz,se), fmul(-2,p)). Screening flags rows whose winner could differ;
// flagged rows are recomputed exactly and merged via atomicMin (d_bits, n) keys.

#define DIM      256
#define TM       128
#define TN       128
#define NSTAGE   3
#define THREADS  256
#define MAX_B    32768
#define MAX_NE   8192
#define THR      5e-7f
#define WINDOW   1.125f

__device__ float g_sz[MAX_B];
__device__ float g_se[MAX_NE];
__device__ __align__(16) __nv_bfloat16 g_ehi[MAX_NE * DIM];
__device__ __align__(16) __nv_bfloat16 g_elo[MAX_NE * DIM];
__device__ int   g_idx[MAX_B];
__device__ int   g_flag[MAX_B];
__device__ int   g_list[MAX_B];
__device__ int   g_cnt;
__device__ unsigned long long g_amin[MAX_B];

// ---- screening smem layout ----
// A_hi [128 rows x 512B swizzled] @0, A_lo @64K, B stages 3x16K @128K, se/reductions after.
#define OFF_A_HI   0
#define OFF_A_LO   65536
#define OFF_B      131072
#define B_STG      16384
#define OFF_SE     180224
#define OFF_RED_D  180736
#define OFF_RED_N  181248
#define OFF_RED_M  181760
#define SMEM_REQ   182272

__device__ __forceinline__ uint32_t smem_u32(const void* p) {
    uint32_t a;
    asm("{ .reg .u64 t; cvta.to.shared.u64 t, %1; cvt.u32.u64 %0, t; }" : "=r"(a) : "l"(p));
    return a;
}
__device__ __forceinline__ void cp16(uint32_t s, const void* g) {
    asm volatile("cp.async.cg.shared.global [%0], [%1], 16;" :: "r"(s), "l"(g));
}
#define CP_COMMIT() asm volatile("cp.async.commit_group;" ::: "memory")
#define CP_WAIT2()  asm volatile("cp.async.wait_group 2;" ::: "memory")
#define CP_WAIT0()  asm volatile("cp.async.wait_group 0;" ::: "memory")

#define LDSM4(r, a) \
    asm volatile("ldmatrix.sync.aligned.m8n8.x4.shared.b16 {%0,%1,%2,%3}, [%4];" \
                 : "=r"((r)[0]), "=r"((r)[1]), "=r"((r)[2]), "=r"((r)[3]) : "r"(a))

#define MMAB(d, a, b0, b1) \
    asm volatile("mma.sync.aligned.m16n8k16.row.col.f32.bf16.bf16.f32 " \
                 "{%0,%1,%2,%3}, {%4,%5,%6,%7}, {%8,%9}, {%0,%1,%2,%3};" \
                 : "+f"((d)[0]), "+f"((d)[1]), "+f"((d)[2]), "+f"((d)[3]) \
                 : "r"((a)[0]), "r"((a)[1]), "r"((a)[2]), "r"((a)[3]), "r"(b0), "r"(b1))

// swizzled 16B-group offsets: bank-group = (g^(row&7)) -> conflict-free ldmatrix
__device__ __forceinline__ uint32_t swzA(int row, int g) {   // 512B rows, g in 0..31
    return (uint32_t)(row * 512 + ((g ^ (row & 7)) << 4));
}
__device__ __forceinline__ uint32_t swzB(int row, int g) {   // 128B rows, g in 0..7
    return (uint32_t)(row * 128 + ((g ^ (row & 7)) << 4));
}
__device__ __forceinline__ float ulp_of(float d) {
    return __uint_as_float(__float_as_uint(d) & 0xFF800000u) * 1.1920929e-7f;
}
__device__ __forceinline__ void splitpair(float x, float y, uint32_t& hi, uint32_t& lo) {
    __nv_bfloat16 xh = __float2bfloat16(x), yh = __float2bfloat16(y);
    __nv_bfloat16 xl = __float2bfloat16(x - __bfloat162float(xh));
    __nv_bfloat16 yl = __float2bfloat16(y - __bfloat162float(yh));
    hi = (uint32_t)__bfloat16_as_ushort(xh) | ((uint32_t)__bfloat16_as_ushort(yh) << 16);
    lo = (uint32_t)__bfloat16_as_ushort(xl) | ((uint32_t)__bfloat16_as_ushort(yl) << 16);
}

typedef unsigned long long ull;
#define PACK2(d, x, y) \
    asm("mov.b64 %0, {%1, %2};" : "=l"(d) : "r"(__float_as_uint(x)), "r"(__float_as_uint(y)))
#define FMA2(acc, a, b) \
    asm("fma.rn.f32x2 %0, %1, %2, %3;" : "=l"(acc) : "l"(a), "l"(b), "l"(acc))
#define UNPACK2(x, y, d) \
    asm("mov.b64 {%0, %1}, %2;" : "=r"(x), "=r"(y) : "l"(d))

// ---------------- prep kernels ----------------
__global__ void row_sumsq_kernel(const float* __restrict__ x, float* __restrict__ o, int rows) {
    int w = (int)((blockIdx.x * blockDim.x + threadIdx.x) >> 5);
    int lane = threadIdx.x & 31;
    if (w >= rows) return;
    const float4* r = (const float4*)(x + (size_t)w * DIM);
    float4 v0 = r[lane * 2];
    float4 v1 = r[lane * 2 + 1];
    float s = v0.x * v0.x;
    s += v0.y * v0.y; s += v0.z * v0.z; s += v0.w * v0.w;
    s += v1.x * v1.x; s += v1.y * v1.y; s += v1.z * v1.z; s += v1.w * v1.w;
#pragma unroll
    for (int off = 16; off; off >>= 1) s += __shfl_xor_sync(0xffffffffu, s, off);
    if (lane == 0) o[w] = s;
}

__global__ void split_bf16_kernel(const float* __restrict__ x, __nv_bfloat16* __restrict__ hi,
                                  __nv_bfloat16* __restrict__ lo, int n8) {
    int i = blockIdx.x * blockDim.x + threadIdx.x;
    if (i >= n8) return;
    float4 v0 = ((const float4*)x)[i * 2];
    float4 v1 = ((const float4*)x)[i * 2 + 1];
    uint4 h, l;
    splitpair(v0.x, v0.y, h.x, l.x);
    splitpair(v0.z, v0.w, h.y, l.y);
    splitpair(v1.x, v1.y, h.z, l.z);
    splitpair(v1.z, v1.w, h.w, l.w);
    ((uint4*)hi)[i] = h;
    ((uint4*)lo)[i] = l;
}

__global__ void init_kernel(int B) {
    int i = blockIdx.x * blockDim.x + threadIdx.x;
    if (i < B) g_amin[i] = ~0ull;
    if (i == 0) g_cnt = 0;
}

// ---------------- pass 1: bf16 3-term MMA + certification ----------------
__global__ void __launch_bounds__(THREADS, 1)
vq_mma_kernel(const float* __restrict__ z,
              const __nv_bfloat16* __restrict__ ehi, const __nv_bfloat16* __restrict__ elo,
              const float* __restrict__ sz, const float* __restrict__ se, int NE)
{
    extern __shared__ char sp[];
    const uint32_t sb = smem_u32(sp);

    const int tid  = threadIdx.x;
    const int lane = tid & 31;
    const int wid  = tid >> 5;
    const int wm   = (wid & 3) * 32;
    const int wn   = (wid >> 2) * 64;
    const int bbase = blockIdx.x * TM;
    const int NTILE = NE / TN;
    const int NCHK  = NTILE * 8;     // 32-k chunks

    const int lrowA = lane & 15;
    const int gselA = lane >> 4;
    const int lrowB = (lane & 7) + ((lane >> 4) << 3);
    const int gselB = (lane >> 3) & 1;

    float d1[4] = {FLT_MAX, FLT_MAX, FLT_MAX, FLT_MAX};
    int   n1[4] = {0, 0, 0, 0};
    float dnm[4] = {FLT_MAX, FLT_MAX, FLT_MAX, FLT_MAX};

    float szr[4];
#pragma unroll
    for (int s = 0; s < 4; s++)
        szr[s] = __ldg(sz + bbase + wm + (s >> 1) * 16 + (s & 1) * 8 + (lane >> 2));

    float acc[2][8][4];
#pragma unroll
    for (int mt = 0; mt < 2; mt++)
#pragma unroll
        for (int nt = 0; nt < 8; nt++)
#pragma unroll
            for (int k = 0; k < 4; k++) acc[mt][nt][k] = 0.0f;

    // B chunk producer: 128 n-rows x (32k hi | 32k lo) bf16 = 128B/row swizzled
    auto issue_chunk = [&](int i, int stage) {
        int c = i & 7, t = i >> 3;
        uint32_t sB = sb + OFF_B + stage * B_STG;
        const __nv_bfloat16* gh = ehi + (size_t)(t * TN) * DIM + c * 32;
        const __nv_bfloat16* gl = elo + (size_t)(t * TN) * DIM + c * 32;
#pragma unroll
        for (int it = 0; it < 4; it++) {
            int idx = tid + it * 256;
            int row = idx >> 3, g = idx & 7;
            const void* src = (g < 4) ? (const void*)(gh + (size_t)row * DIM + g * 8)
                                      : (const void*)(gl + (size_t)row * DIM + (g - 4) * 8);
            cp16(sB + swzB(row, g), src);
        }
        CP_COMMIT();
    };

    issue_chunk(0, 0);
    issue_chunk(1, 1);
    issue_chunk(2, 2);

    // ---- persistent A fill: split z rows to bf16 hi/lo in swizzled SMEM ----
    {
        int r = tid >> 1, half = tid & 1;
        const float4* zrow = (const float4*)(z + (size_t)(bbase + r) * DIM + half * 128);
#pragma unroll 4
        for (int q = 0; q < 16; q++) {
            float4 v0 = zrow[q * 2], v1 = zrow[q * 2 + 1];
            uint4 h, l;
            splitpair(v0.x, v0.y, h.x, l.x);
            splitpair(v0.z, v0.w, h.y, l.y);
            splitpair(v1.x, v1.y, h.z, l.z);
            splitpair(v1.z, v1.w, h.w, l.w);
            uint32_t off = swzA(r, half * 16 + q);
            *(uint4*)(sp + OFF_A_HI + off) = h;
            *(uint4*)(sp + OFF_A_LO + off) = l;
        }
    }

    float* sm_se = (float*)(sp + OFF_SE);

#pragma unroll 1
    for (int i = 0; i < NCHK; i++) {
        int stage = i % NSTAGE;
        CP_WAIT2();
        __syncthreads();      // also covers A-fill readiness on i==0

        if ((i & 7) == 0 && tid < 32)
            ((float4*)sm_se)[tid] = ((const float4*)(se + (i >> 3) * TN))[tid];

        uint32_t sB = sb + OFF_B + stage * B_STG;
#pragma unroll
        for (int ksl = 0; ksl < 2; ksl++) {
            int ksg = ((i & 7) << 1) | ksl;      // global k16 index 0..15
            uint32_t ah[2][4], al[2][4], bh[4][4], bl[4][4];
#pragma unroll
            for (int mt = 0; mt < 2; mt++) {
                int row = wm + mt * 16 + lrowA;
                uint32_t ad = sb + OFF_A_HI + swzA(row, ksg * 2 + gselA);
                LDSM4(ah[mt], ad);
                LDSM4(al[mt], ad + 65536);
            }
#pragma unroll
            for (int p = 0; p < 4; p++) {
                int row = wn + p * 16 + lrowB;
                LDSM4(bh[p], sB + swzB(row, ksl * 2 + gselB));
                LDSM4(bl[p], sB + swzB(row, 4 + ksl * 2 + gselB));
            }
#pragma unroll
            for (int mt = 0; mt < 2; mt++)
#pragma unroll
                for (int nt = 0; nt < 8; nt++) {
                    int p = nt >> 1, o = (nt & 1) * 2;
                    MMAB(acc[mt][nt], ah[mt], bh[p][o], bh[p][o + 1]);
                    MMAB(acc[mt][nt], al[mt], bh[p][o], bh[p][o + 1]);
                    MMAB(acc[mt][nt], ah[mt], bl[p][o], bl[p][o + 1]);
                }
        }

        if ((i & 7) == 7) {
            int t = i >> 3;
#pragma unroll
            for (int mt = 0; mt < 2; mt++)
#pragma unroll
                for (int half = 0; half < 2; half++) {
                    int slot = mt * 2 + half;
                    float szv = szr[slot];
#pragma unroll
                    for (int nt = 0; nt < 8; nt++)
#pragma unroll
                        for (int j = 0; j < 2; j++) {
                            float p = acc[mt][nt][half * 2 + j];
                            int nl = wn + nt * 8 + (lane & 3) * 2 + j;
                            float tt = __fadd_rn(szv, sm_se[nl]);
                            float q  = __fmul_rn(-2.0f, p);
                            float d  = __fadd_rn(tt, q);
                            float zzv = __fadd_rn(d, -tt);   // exact (Fast2Sum)
                            float r   = __fadd_rn(q, -zzv);  // exact rounding residual
                            bool nm = fabsf(r) >= (0.5f * ulp_of(d) - THR);
                            if (nm && d < dnm[slot]) dnm[slot] = d;
                            int ng = t * TN + nl;
                            if (d < d1[slot]) { d1[slot] = d; n1[slot] = ng; }
                        }
                }
#pragma unroll
            for (int mt = 0; mt < 2; mt++)
#pragma unroll
                for (int nt = 0; nt < 8; nt++)
#pragma unroll
                    for (int k = 0; k < 4; k++) acc[mt][nt][k] = 0.0f;
        }

        __syncthreads();
        if (i + NSTAGE < NCHK) issue_chunk(i + NSTAGE, stage);
    }
    CP_WAIT0();

#pragma unroll
    for (int s = 0; s < 4; s++) {
#pragma unroll
        for (int off = 1; off <= 2; off <<= 1) {
            float od = __shfl_xor_sync(0xffffffffu, d1[s], off);
            int   on = __shfl_xor_sync(0xffffffffu, n1[s], off);
            float om = __shfl_xor_sync(0xffffffffu, dnm[s], off);
            if (od < d1[s] || (od == d1[s] && on < n1[s])) { d1[s] = od; n1[s] = on; }
            if (om < dnm[s]) dnm[s] = om;
        }
    }

    float* sd = (float*)(sp + OFF_RED_D);
    int*   sn = (int*)(sp + OFF_RED_N);
    float* sm = (float*)(sp + OFF_RED_M);
    if (wn == 0 && (lane & 3) == 0) {
#pragma unroll
        for (int s = 0; s < 4; s++) {
            int row = wm + (s >> 1) * 16 + (s & 1) * 8 + (lane >> 2);
            sd[row] = d1[s]; sn[row] = n1[s]; sm[row] = dnm[s];
        }
    }
    __syncthreads();
    if (wn != 0 && (lane & 3) == 0) {
#pragma unroll
        for (int s = 0; s < 4; s++) {
            int row = wm + (s >> 1) * 16 + (s & 1) * 8 + (lane >> 2);
            float od = sd[row]; int on = sn[row]; float om = sm[row];
            if (od < d1[s] || (od == d1[s] && on < n1[s])) { d1[s] = od; n1[s] = on; }
            if (om < dnm[s]) dnm[s] = om;
            g_idx[bbase + row] = n1[s];
            g_flag[bbase + row] = (dnm[s] <= d1[s] + WINDOW * ulp_of(d1[s])) ? 1 : 0;
        }
    }
}

// ---------------- compaction ----------------
__global__ void compact_kernel(int B) {
    int i = blockIdx.x * blockDim.x + threadIdx.x;
    if (i < B && g_flag[i]) {
        int p = atomicAdd(&g_cnt, 1);
        g_list[p] = i;
    }
}

// ---------------- rescue: exact ground-truth numerics, n-partitioned (R8) ----------------
#define RBM 128
#define RBN 128
#define RBK 32
#define SLICE_N 1024

__global__ void __launch_bounds__(256, 1)
rescue3_kernel(const float* __restrict__ z, const float* __restrict__ emb,
               const float* __restrict__ sz, const float* __restrict__ se, int NE)
{
    extern __shared__ float smem[];
    float* sm_z  = smem;
    float* sm_e  = smem + DIM * RBM;
    float* run_d = sm_e + RBK * RBN;
    int*   run_n = (int*)(run_d + RBM);

    const int tid = threadIdx.x;
    const int tx = tid & 15;
    const int ty = tid >> 4;
    const int cnt = g_cnt;
    const int ngrp = (cnt + RBM - 1) / RBM;
    const int nslice = NE / SLICE_N;
    const int nitems = ngrp * nslice;

    for (int item = blockIdx.x; item < nitems; item += gridDim.x) {
        const int grp = item / nslice;
        const int slice = item - grp * nslice;
        const int n0 = slice * SLICE_N;

        {
            int r = tid >> 1, half = tid & 1;
            int li = grp * RBM + r;
            int grow = g_list[li < cnt ? li : cnt - 1];
            const float4* src = (const float4*)(z + (size_t)grow * DIM + half * 128);
#pragma unroll
            for (int qq = 0; qq < 32; qq++) {
                float4 v = src[qq];
                int k = half * 128 + qq * 4;
                sm_z[(k + 0) * RBM + r] = v.x;
                sm_z[(k + 1) * RBM + r] = v.y;
                sm_z[(k + 2) * RBM + r] = v.z;
                sm_z[(k + 3) * RBM + r] = v.w;
            }
        }
        if (tid < RBM) { run_d[tid] = FLT_MAX; run_n[tid] = 0; }

        float szr[8];
#pragma unroll
        for (int i = 0; i < 8; i++) {
            int li = grp * RBM + ty * 8 + i;
            szr[i] = __ldg(sz + g_list[li < cnt ? li : cnt - 1]);
        }
        __syncthreads();

        const int ec = tid >> 1;
        const int ekh = (tid & 1) * 16;

#pragma unroll 1
        for (int nbase = n0; nbase < n0 + SLICE_N; nbase += RBN) {
            ull acc2[8][4];
#pragma unroll
            for (int i = 0; i < 8; i++)
#pragma unroll
                for (int j = 0; j < 4; j++) acc2[i][j] = 0ull;

            float4 pf0, pf1, pf2, pf3;
            {
                const float4* src = (const float4*)(emb + (size_t)(nbase + ec) * DIM + ekh);
                pf0 = src[0]; pf1 = src[1]; pf2 = src[2]; pf3 = src[3];
            }

#pragma unroll 1
            for (int s = 0; s < DIM / RBK; s++) {
                __syncthreads();
                {
                    float* dst = sm_e + ec;
                    dst[(ekh + 0)  * RBN] = pf0.x; dst[(ekh + 1)  * RBN] = pf0.y;
                    dst[(ekh + 2)  * RBN] = pf0.z; dst[(ekh + 3)  * RBN] = pf0.w;
                    dst[(ekh + 4)  * RBN] = pf1.x; dst[(ekh + 5)  * RBN] = pf1.y;
                    dst[(ekh + 6)  * RBN] = pf1.z; dst[(ekh + 7)  * RBN] = pf1.w;
                    dst[(ekh + 8)  * RBN] = pf2.x; dst[(ekh + 9)  * RBN] = pf2.y;
                    dst[(ekh + 10) * RBN] = pf2.z; dst[(ekh + 11) * RBN] = pf2.w;
                    dst[(ekh + 12) * RBN] = pf3.x; dst[(ekh + 13) * RBN] = pf3.y;
                    dst[(ekh + 14) * RBN] = pf3.z; dst[(ekh + 15) * RBN] = pf3.w;
                }
                __syncthreads();
                if (s + 1 < DIM / RBK) {
                    const float4* src = (const float4*)(emb + (size_t)(nbase + ec) * DIM
                                                        + (s + 1) * RBK + ekh);
                    pf0 = src[0]; pf1 = src[1]; pf2 = src[2]; pf3 = src[3];
                }
                const float* zs = sm_z + (s * RBK) * RBM + ty * 8;
                const float* es = sm_e + tx * 8;
#pragma unroll 8
                for (int kk = 0; kk < RBK; kk++) {
                    float4 a0 = *(const float4*)(zs + kk * RBM);
                    float4 a1 = *(const float4*)(zs + kk * RBM + 4);
                    float4 b0 = *(const float4*)(es + kk * RBN);
                    float4 b1 = *(const float4*)(es + kk * RBN + 4);
                    ull bb0, bb1, bb2, bb3;
                    PACK2(bb0, b0.x, b0.y); PACK2(bb1, b0.z, b0.w);
                    PACK2(bb2, b1.x, b1.y); PACK2(bb3, b1.z, b1.w);
                    float av[8] = {a0.x, a0.y, a0.z, a0.w, a1.x, a1.y, a1.z, a1.w};
#pragma unroll
                    for (int i = 0; i < 8; i++) {
                        ull aa; PACK2(aa, av[i], av[i]);
                        FMA2(acc2[i][0], aa, bb0);
                        FMA2(acc2[i][1], aa, bb1);
                        FMA2(acc2[i][2], aa, bb2);
                        FMA2(acc2[i][3], aa, bb3);
                    }
                }
            }

            float4 se0 = *(const float4*)(se + nbase + tx * 8);
            float4 se1 = *(const float4*)(se + nbase + tx * 8 + 4);
            float sen[8] = {se0.x, se0.y, se0.z, se0.w, se1.x, se1.y, se1.z, se1.w};
#pragma unroll
            for (int i = 0; i < 8; i++) {
                float bdv = FLT_MAX; int bnv = 0;
#pragma unroll
                for (int j2 = 0; j2 < 4; j2++) {
                    unsigned plo_u, phi_u;
                    UNPACK2(plo_u, phi_u, acc2[i][j2]);
                    float plo = __uint_as_float(plo_u);
                    float phi = __uint_as_float(phi_u);
                    float t0 = __fadd_rn(szr[i], sen[2 * j2]);
                    float t1 = __fadd_rn(szr[i], sen[2 * j2 + 1]);
                    float dd0 = __fadd_rn(t0, __fmul_rn(-2.0f, plo));
                    float dd1 = __fadd_rn(t1, __fmul_rn(-2.0f, phi));
                    if (dd0 < bdv) { bdv = dd0; bnv = nbase + tx * 8 + 2 * j2; }
                    if (dd1 < bdv) { bdv = dd1; bnv = nbase + tx * 8 + 2 * j2 + 1; }
                }
#pragma unroll
                for (int off = 8; off; off >>= 1) {
                    float od = __shfl_down_sync(0xffffffffu, bdv, off, 16);
                    int   on = __shfl_down_sync(0xffffffffu, bnv, off, 16);
                    if (od < bdv || (od == bdv && on < bnv)) { bdv = od; bnv = on; }
                }
                if (tx == 0) {
                    int rr = ty * 8 + i;
                    if (bdv < run_d[rr]) { run_d[rr] = bdv; run_n[rr] = bnv; }
                }
            }
        }

        __syncthreads();
        if (tid < RBM) {
            int li = grp * RBM + tid;
            if (li < cnt) {
                unsigned long long key =
                    ((unsigned long long)__float_as_uint(run_d[tid]) << 32)
                    | (unsigned)run_n[tid];
                atomicMin(&g_amin[g_list[li]], key);
            }
        }
        __syncthreads();
    }
}

// ---------------- output gather ----------------
__global__ void gather_kernel(const float* __restrict__ emb, float* __restrict__ outp,
                              int B, int mode, long long idx_off)
{
    int w = (int)((blockIdx.x * blockDim.x + threadIdx.x) >> 5);
    int lane = threadIdx.x & 31;
    if (w >= B) return;
    int idx = g_flag[w] ? (int)(unsigned)(g_amin[w] & 0xFFFFFFFFull) : g_idx[w];
    if (mode & 1) {
        const float4* src = (const float4*)(emb + (size_t)idx * DIM);
        float4* dst = (float4*)(outp + (size_t)w * DIM);
        dst[lane] = src[lane];
        dst[lane + 32] = src[lane + 32];
    }
    if ((mode & 2) && lane == 0) outp[idx_off + w] = (float)idx;
}

extern "C" void kernel_launch(void* const* d_in, const int* in_sizes, int n_in,
                              void* d_out, int out_size) {
    const float* z   = (const float*)d_in[0];
    const float* emb = (const float*)d_in[1];
    float* outp = (float*)d_out;

    int B  = in_sizes[0] / DIM;
    int NE = in_sizes[1] / DIM;

    float *sz_p, *se_p;
    __nv_bfloat16 *ehi_p, *elo_p;
    cudaGetSymbolAddress((void**)&sz_p,  g_sz);
    cudaGetSymbolAddress((void**)&se_p,  g_se);
    cudaGetSymbolAddress((void**)&ehi_p, g_ehi);
    cudaGetSymbolAddress((void**)&elo_p, g_elo);

    row_sumsq_kernel<<<(B + 7) / 8, 256>>>(z, sz_p, B);
    row_sumsq_kernel<<<(NE + 7) / 8, 256>>>(emb, se_p, NE);
    int ne8 = NE * DIM / 8;
    split_bf16_kernel<<<(ne8 + 255) / 256, 256>>>(emb, ehi_p, elo_p, ne8);

    init_kernel<<<(B + 255) / 256, 256>>>(B);

    cudaFuncSetAttribute(vq_mma_kernel, cudaFuncAttributeMaxDynamicSharedMemorySize, SMEM_REQ);
    vq_mma_kernel<<<B / TM, THREADS, SMEM_REQ>>>(z, ehi_p, elo_p, sz_p, se_p, NE);

    compact_kernel<<<(B + 255) / 256, 256>>>(B);

    size_t rs_smem = (size_t)(DIM * RBM + RBK * RBN + RBM) * sizeof(float) + RBM * sizeof(int);
    cudaFuncSetAttribute(rescue3_kernel, cudaFuncAttributeMaxDynamicSharedMemorySize, (int)rs_smem);
    rescue3_kernel<<<512, 256, rs_smem>>>(z, emb, sz_p, se_p, NE);

    long long zq_elems = (long long)B * DIM;
    int mode; long long idx_off;
    if ((long long)out_size >= zq_elems + B) { mode = 3; idx_off = zq_elems; }
    else if ((long long)out_size >= zq_elems) { mode = 1; idx_off = 0; }
    else { mode = 2; idx_off = 0; }

    gather_kernel<<<(B * 32 + 255) / 256, 256>>>(emb, outp, B, mode, idx_off);
}

// round 10
// speedup vs baseline: 4.0262x; 1.0664x over previous
#include <cuda_runtime.h>
#include <cuda_bf16.h>
#include <cstdint>
#include <cfloat>

// IBQ VQ: bf16 3-term mma.sync screening (persistent-A, N-sliced grid=1024) +
// soundness certification + fine-grained exact-fp32 tiled rescue.
//   d[b,n] = (sz[b]+se[n]) - 2*dot(z[b],e[n]);  idx=argmin (first index on ties)
// Ground truth (empirically == reference, R5/R6/R8/R9): sequential-k fp32 FMA chain,
// d = fadd(fadd(sz,se), fmul(-2,p)). Screening flags rows whose winner could differ;
// flagged rows are recomputed exactly; all merges via atomicMin on (d_bits,n) keys.

#define DIM      256
#define TM       128
#define TN       128
#define NSTAGE   3
#define THREADS  256
#define MAX_B    32768
#define MAX_NE   8192
#define THR      5e-7f
#define WINDOW   1.125f
#define NSLICE   4            // screening N-slices

__device__ float g_sz[MAX_B];
__device__ float g_se[MAX_NE];
__device__ __align__(16) __nv_bfloat16 g_ehi[MAX_NE * DIM];
__device__ __align__(16) __nv_bfloat16 g_elo[MAX_NE * DIM];
__device__ int   g_idx[MAX_B];
__device__ int   g_flag[MAX_B];
__device__ int   g_list[MAX_B];
__device__ int   g_cnt;
__device__ unsigned long long g_smin[MAX_B];   // screening winner key
__device__ unsigned int      g_dnm[MAX_B];     // min d over midpoint-near candidates
__device__ unsigned long long g_rmin[MAX_B];   // rescue winner key

// ---- screening smem layout ----
#define OFF_A_HI   0
#define OFF_A_LO   65536
#define OFF_B      131072
#define B_STG      16384
#define OFF_SE     180224
#define OFF_RED_D  180736
#define OFF_RED_N  181248
#define OFF_RED_M  181760
#define SMEM_REQ   182272

__device__ __forceinline__ uint32_t smem_u32(const void* p) {
    uint32_t a;
    asm("{ .reg .u64 t; cvta.to.shared.u64 t, %1; cvt.u32.u64 %0, t; }" : "=r"(a) : "l"(p));
    return a;
}
__device__ __forceinline__ void cp16(uint32_t s, const void* g) {
    asm volatile("cp.async.cg.shared.global [%0], [%1], 16;" :: "r"(s), "l"(g));
}
#define CP_COMMIT() asm volatile("cp.async.commit_group;" ::: "memory")
#define CP_WAIT2()  asm volatile("cp.async.wait_group 2;" ::: "memory")
#define CP_WAIT0()  asm volatile("cp.async.wait_group 0;" ::: "memory")

#define LDSM4(r, a) \
    asm volatile("ldmatrix.sync.aligned.m8n8.x4.shared.b16 {%0,%1,%2,%3}, [%4];" \
                 : "=r"((r)[0]), "=r"((r)[1]), "=r"((r)[2]), "=r"((r)[3]) : "r"(a))

#define MMAB(d, a, b0, b1) \
    asm volatile("mma.sync.aligned.m16n8k16.row.col.f32.bf16.bf16.f32 " \
                 "{%0,%1,%2,%3}, {%4,%5,%6,%7}, {%8,%9}, {%0,%1,%2,%3};" \
                 : "+f"((d)[0]), "+f"((d)[1]), "+f"((d)[2]), "+f"((d)[3]) \
                 : "r"((a)[0]), "r"((a)[1]), "r"((a)[2]), "r"((a)[3]), "r"(b0), "r"(b1))

__device__ __forceinline__ uint32_t swzA(int row, int g) {   // 512B rows, g in 0..31
    return (uint32_t)(row * 512 + ((g ^ (row & 7)) << 4));
}
__device__ __forceinline__ uint32_t swzB(int row, int g) {   // 128B rows, g in 0..7
    return (uint32_t)(row * 128 + ((g ^ (row & 7)) << 4));
}
__device__ __forceinline__ float ulp_of(float d) {
    return __uint_as_float(__float_as_uint(d) & 0xFF800000u) * 1.1920929e-7f;
}
__device__ __forceinline__ void splitpair(float x, float y, uint32_t& hi, uint32_t& lo) {
    __nv_bfloat16 xh = __float2bfloat16(x), yh = __float2bfloat16(y);
    __nv_bfloat16 xl = __float2bfloat16(x - __bfloat162float(xh));
    __nv_bfloat16 yl = __float2bfloat16(y - __bfloat162float(yh));
    hi = (uint32_t)__bfloat16_as_ushort(xh) | ((uint32_t)__bfloat16_as_ushort(yh) << 16);
    lo = (uint32_t)__bfloat16_as_ushort(xl) | ((uint32_t)__bfloat16_as_ushort(yl) << 16);
}

typedef unsigned long long ull;
#define PACK2(d, x, y) \
    asm("mov.b64 %0, {%1, %2};" : "=l"(d) : "r"(__float_as_uint(x)), "r"(__float_as_uint(y)))
#define FMA2(acc, a, b) \
    asm("fma.rn.f32x2 %0, %1, %2, %3;" : "=l"(acc) : "l"(a), "l"(b), "l"(acc))
#define UNPACK2(x, y, d) \
    asm("mov.b64 {%0, %1}, %2;" : "=r"(x), "=r"(y) : "l"(d))

// ---------------- prep kernels ----------------
__global__ void row_sumsq_kernel(const float* __restrict__ x, float* __restrict__ o, int rows) {
    int w = (int)((blockIdx.x * blockDim.x + threadIdx.x) >> 5);
    int lane = threadIdx.x & 31;
    if (w >= rows) return;
    const float4* r = (const float4*)(x + (size_t)w * DIM);
    float4 v0 = r[lane * 2];
    float4 v1 = r[lane * 2 + 1];
    float s = v0.x * v0.x;
    s += v0.y * v0.y; s += v0.z * v0.z; s += v0.w * v0.w;
    s += v1.x * v1.x; s += v1.y * v1.y; s += v1.z * v1.z; s += v1.w * v1.w;
#pragma unroll
    for (int off = 16; off; off >>= 1) s += __shfl_xor_sync(0xffffffffu, s, off);
    if (lane == 0) o[w] = s;
}

__global__ void split_bf16_kernel(const float* __restrict__ x, __nv_bfloat16* __restrict__ hi,
                                  __nv_bfloat16* __restrict__ lo, int n8) {
    int i = blockIdx.x * blockDim.x + threadIdx.x;
    if (i >= n8) return;
    float4 v0 = ((const float4*)x)[i * 2];
    float4 v1 = ((const float4*)x)[i * 2 + 1];
    uint4 h, l;
    splitpair(v0.x, v0.y, h.x, l.x);
    splitpair(v0.z, v0.w, h.y, l.y);
    splitpair(v1.x, v1.y, h.z, l.z);
    splitpair(v1.z, v1.w, h.w, l.w);
    ((uint4*)hi)[i] = h;
    ((uint4*)lo)[i] = l;
}

__global__ void init_kernel(int B) {
    int i = blockIdx.x * blockDim.x + threadIdx.x;
    if (i < B) { g_smin[i] = ~0ull; g_rmin[i] = ~0ull; g_dnm[i] = 0xFFFFFFFFu; }
    if (i == 0) g_cnt = 0;
}

// ---------------- pass 1: bf16 3-term MMA + certification (N-sliced) ----------------
__global__ void __launch_bounds__(THREADS, 1)
vq_mma_kernel(const float* __restrict__ z,
              const __nv_bfloat16* __restrict__ ehi, const __nv_bfloat16* __restrict__ elo,
              const float* __restrict__ sz, const float* __restrict__ se, int NE, int nrow)
{
    extern __shared__ char sp[];
    const uint32_t sb = smem_u32(sp);

    const int tid  = threadIdx.x;
    const int lane = tid & 31;
    const int wid  = tid >> 5;
    const int wm   = (wid & 3) * 32;
    const int wn   = (wid >> 2) * 64;
    // slice-major: wave-1 CTAs share the same B slice range across different row tiles
    const int rowblk = blockIdx.x % nrow;
    const int slice  = blockIdx.x / nrow;
    const int bbase  = rowblk * TM;
    const int NE_SL  = NE / NSLICE;               // 2048
    const int t0     = slice * (NE_SL / TN);      // first n-tile of this slice
    const int NCHK   = (NE_SL / TN) * 8;          // 128 k-chunks

    const int lrowA = lane & 15;
    const int gselA = lane >> 4;
    const int lrowB = (lane & 7) + ((lane >> 4) << 3);
    const int gselB = (lane >> 3) & 1;

    float d1[4] = {FLT_MAX, FLT_MAX, FLT_MAX, FLT_MAX};
    int   n1[4] = {0, 0, 0, 0};
    float dnm[4] = {FLT_MAX, FLT_MAX, FLT_MAX, FLT_MAX};

    float szr[4];
#pragma unroll
    for (int s = 0; s < 4; s++)
        szr[s] = __ldg(sz + bbase + wm + (s >> 1) * 16 + (s & 1) * 8 + (lane >> 2));

    float acc[2][8][4];
#pragma unroll
    for (int mt = 0; mt < 2; mt++)
#pragma unroll
        for (int nt = 0; nt < 8; nt++)
#pragma unroll
            for (int k = 0; k < 4; k++) acc[mt][nt][k] = 0.0f;

    auto issue_chunk = [&](int i, int stage) {
        int c = i & 7, t = t0 + (i >> 3);
        uint32_t sB = sb + OFF_B + stage * B_STG;
        const __nv_bfloat16* gh = ehi + (size_t)(t * TN) * DIM + c * 32;
        const __nv_bfloat16* gl = elo + (size_t)(t * TN) * DIM + c * 32;
#pragma unroll
        for (int it = 0; it < 4; it++) {
            int idx = tid + it * 256;
            int row = idx >> 3, g = idx & 7;
            const void* src = (g < 4) ? (const void*)(gh + (size_t)row * DIM + g * 8)
                                      : (const void*)(gl + (size_t)row * DIM + (g - 4) * 8);
            cp16(sB + swzB(row, g), src);
        }
        CP_COMMIT();
    };

    issue_chunk(0, 0);
    issue_chunk(1, 1);
    issue_chunk(2, 2);

    // ---- persistent A fill: split z rows to bf16 hi/lo in swizzled SMEM ----
    {
        int r = tid >> 1, half = tid & 1;
        const float4* zrow = (const float4*)(z + (size_t)(bbase + r) * DIM + half * 128);
#pragma unroll 4
        for (int q = 0; q < 16; q++) {
            float4 v0 = zrow[q * 2], v1 = zrow[q * 2 + 1];
            uint4 h, l;
            splitpair(v0.x, v0.y, h.x, l.x);
            splitpair(v0.z, v0.w, h.y, l.y);
            splitpair(v1.x, v1.y, h.z, l.z);
            splitpair(v1.z, v1.w, h.w, l.w);
            uint32_t off = swzA(r, half * 16 + q);
            *(uint4*)(sp + OFF_A_HI + off) = h;
            *(uint4*)(sp + OFF_A_LO + off) = l;
        }
    }

    float* sm_se = (float*)(sp + OFF_SE);

#pragma unroll 1
    for (int i = 0; i < NCHK; i++) {
        int stage = i % NSTAGE;
        CP_WAIT2();
        __syncthreads();      // also covers A-fill readiness on i==0

        if ((i & 7) == 0 && tid < 32)
            ((float4*)sm_se)[tid] = ((const float4*)(se + (t0 + (i >> 3)) * TN))[tid];

        uint32_t sB = sb + OFF_B + stage * B_STG;
#pragma unroll
        for (int ksl = 0; ksl < 2; ksl++) {
            int ksg = ((i & 7) << 1) | ksl;
            uint32_t ah[2][4], al[2][4], bh[4][4], bl[4][4];
#pragma unroll
            for (int mt = 0; mt < 2; mt++) {
                int row = wm + mt * 16 + lrowA;
                uint32_t ad = sb + OFF_A_HI + swzA(row, ksg * 2 + gselA);
                LDSM4(ah[mt], ad);
                LDSM4(al[mt], ad + 65536);
            }
#pragma unroll
            for (int p = 0; p < 4; p++) {
                int row = wn + p * 16 + lrowB;
                LDSM4(bh[p], sB + swzB(row, ksl * 2 + gselB));
                LDSM4(bl[p], sB + swzB(row, 4 + ksl * 2 + gselB));
            }
#pragma unroll
            for (int mt = 0; mt < 2; mt++)
#pragma unroll
                for (int nt = 0; nt < 8; nt++) {
                    int p = nt >> 1, o = (nt & 1) * 2;
                    MMAB(acc[mt][nt], ah[mt], bh[p][o], bh[p][o + 1]);
                    MMAB(acc[mt][nt], al[mt], bh[p][o], bh[p][o + 1]);
                    MMAB(acc[mt][nt], ah[mt], bl[p][o], bl[p][o + 1]);
                }
        }

        if ((i & 7) == 7) {
            int t = t0 + (i >> 3);
#pragma unroll
            for (int mt = 0; mt < 2; mt++)
#pragma unroll
                for (int half = 0; half < 2; half++) {
                    int slot = mt * 2 + half;
                    float szv = szr[slot];
#pragma unroll
                    for (int nt = 0; nt < 8; nt++)
#pragma unroll
                        for (int j = 0; j < 2; j++) {
                            float p = acc[mt][nt][half * 2 + j];
                            int nl = wn + nt * 8 + (lane & 3) * 2 + j;
                            float tt = __fadd_rn(szv, sm_se[nl]);
                            float q  = __fmul_rn(-2.0f, p);
                            float d  = __fadd_rn(tt, q);
                            float zzv = __fadd_rn(d, -tt);   // exact (Fast2Sum)
                            float r   = __fadd_rn(q, -zzv);  // exact rounding residual
                            bool nm = fabsf(r) >= (0.5f * ulp_of(d) - THR);
                            if (nm && d < dnm[slot]) dnm[slot] = d;
                            int ng = t * TN + nl;
                            if (d < d1[slot]) { d1[slot] = d; n1[slot] = ng; }
                        }
                }
#pragma unroll
            for (int mt = 0; mt < 2; mt++)
#pragma unroll
                for (int nt = 0; nt < 8; nt++)
#pragma unroll
                    for (int k = 0; k < 4; k++) acc[mt][nt][k] = 0.0f;
        }

        __syncthreads();
        if (i + NSTAGE < NCHK) issue_chunk(i + NSTAGE, stage);
    }
    CP_WAIT0();

#pragma unroll
    for (int s = 0; s < 4; s++) {
#pragma unroll
        for (int off = 1; off <= 2; off <<= 1) {
            float od = __shfl_xor_sync(0xffffffffu, d1[s], off);
            int   on = __shfl_xor_sync(0xffffffffu, n1[s], off);
            float om = __shfl_xor_sync(0xffffffffu, dnm[s], off);
            if (od < d1[s] || (od == d1[s] && on < n1[s])) { d1[s] = od; n1[s] = on; }
            if (om < dnm[s]) dnm[s] = om;
        }
    }

    float* sd = (float*)(sp + OFF_RED_D);
    int*   sn = (int*)(sp + OFF_RED_N);
    float* sm = (float*)(sp + OFF_RED_M);
    if (wn == 0 && (lane & 3) == 0) {
#pragma unroll
        for (int s = 0; s < 4; s++) {
            int row = wm + (s >> 1) * 16 + (s & 1) * 8 + (lane >> 2);
            sd[row] = d1[s]; sn[row] = n1[s]; sm[row] = dnm[s];
        }
    }
    __syncthreads();
    if (wn != 0 && (lane & 3) == 0) {
#pragma unroll
        for (int s = 0; s < 4; s++) {
            int row = wm + (s >> 1) * 16 + (s & 1) * 8 + (lane >> 2);
            float od = sd[row]; int on = sn[row]; float om = sm[row];
            if (od < d1[s] || (od == d1[s] && on < n1[s])) { d1[s] = od; n1[s] = on; }
            if (om < dnm[s]) dnm[s] = om;
            ull key = ((ull)__float_as_uint(d1[s]) << 32) | (unsigned)n1[s];
            atomicMin(&g_smin[bbase + row], key);
            atomicMin(&g_dnm[bbase + row], __float_as_uint(dnm[s]));
        }
    }
}

// ---------------- flag decision + compaction ----------------
__global__ void flag_compact_kernel(int B) {
    int i = blockIdx.x * blockDim.x + threadIdx.x;
    if (i >= B) return;
    ull key = g_smin[i];
    float d1 = __uint_as_float((unsigned)(key >> 32));
    float dm = __uint_as_float(g_dnm[i]);
    g_idx[i] = (int)(unsigned)(key & 0xFFFFFFFFull);
    int fl = (dm <= d1 + WINDOW * ulp_of(d1)) ? 1 : 0;
    g_flag[i] = fl;
    if (fl) {
        int p = atomicAdd(&g_cnt, 1);
        g_list[p] = i;
    }
}

// ---------------- rescue: exact ground-truth numerics, fine-grained ----------------
#define RBM 128
#define RBN 128
#define RBK 32
#define SLICE_N 256

__global__ void __launch_bounds__(256, 1)
rescue3_kernel(const float* __restrict__ z, const float* __restrict__ emb,
               const float* __restrict__ sz, const float* __restrict__ se, int NE)
{
    extern __shared__ float smem[];
    float* sm_z  = smem;
    float* sm_e  = smem + DIM * RBM;
    float* run_d = sm_e + RBK * RBN;
    int*   run_n = (int*)(run_d + RBM);

    const int tid = threadIdx.x;
    const int tx = tid & 15;
    const int ty = tid >> 4;
    const int cnt = g_cnt;
    const int ngrp = (cnt + RBM - 1) / RBM;
    const int nslice = NE / SLICE_N;     // 32
    const int nitems = ngrp * nslice;

    for (int item = blockIdx.x; item < nitems; item += gridDim.x) {
        const int grp = item / nslice;
        const int slice = item - grp * nslice;
        const int n0 = slice * SLICE_N;

        {
            int r = tid >> 1, half = tid & 1;
            int li = grp * RBM + r;
            int grow = g_list[li < cnt ? li : cnt - 1];
            const float4* src = (const float4*)(z + (size_t)grow * DIM + half * 128);
#pragma unroll
            for (int qq = 0; qq < 32; qq++) {
                float4 v = src[qq];
                int k = half * 128 + qq * 4;
                sm_z[(k + 0) * RBM + r] = v.x;
                sm_z[(k + 1) * RBM + r] = v.y;
                sm_z[(k + 2) * RBM + r] = v.z;
                sm_z[(k + 3) * RBM + r] = v.w;
            }
        }
        if (tid < RBM) { run_d[tid] = FLT_MAX; run_n[tid] = 0; }

        float szr[8];
#pragma unroll
        for (int i = 0; i < 8; i++) {
            int li = grp * RBM + ty * 8 + i;
            szr[i] = __ldg(sz + g_list[li < cnt ? li : cnt - 1]);
        }
        __syncthreads();

        const int ec = tid >> 1;
        const int ekh = (tid & 1) * 16;

#pragma unroll 1
        for (int nbase = n0; nbase < n0 + SLICE_N; nbase += RBN) {
            ull acc2[8][4];
#pragma unroll
            for (int i = 0; i < 8; i++)
#pragma unroll
                for (int j = 0; j < 4; j++) acc2[i][j] = 0ull;

            float4 pf0, pf1, pf2, pf3;
            {
                const float4* src = (const float4*)(emb + (size_t)(nbase + ec) * DIM + ekh);
                pf0 = src[0]; pf1 = src[1]; pf2 = src[2]; pf3 = src[3];
            }

#pragma unroll 1
            for (int s = 0; s < DIM / RBK; s++) {
                __syncthreads();
                {
                    float* dst = sm_e + ec;
                    dst[(ekh + 0)  * RBN] = pf0.x; dst[(ekh + 1)  * RBN] = pf0.y;
                    dst[(ekh + 2)  * RBN] = pf0.z; dst[(ekh + 3)  * RBN] = pf0.w;
                    dst[(ekh + 4)  * RBN] = pf1.x; dst[(ekh + 5)  * RBN] = pf1.y;
                    dst[(ekh + 6)  * RBN] = pf1.z; dst[(ekh + 7)  * RBN] = pf1.w;
                    dst[(ekh + 8)  * RBN] = pf2.x; dst[(ekh + 9)  * RBN] = pf2.y;
                    dst[(ekh + 10) * RBN] = pf2.z; dst[(ekh + 11) * RBN] = pf2.w;
                    dst[(ekh + 12) * RBN] = pf3.x; dst[(ekh + 13) * RBN] = pf3.y;
                    dst[(ekh + 14) * RBN] = pf3.z; dst[(ekh + 15) * RBN] = pf3.w;
                }
                __syncthreads();
                if (s + 1 < DIM / RBK) {
                    const float4* src = (const float4*)(emb + (size_t)(nbase + ec) * DIM
                                                        + (s + 1) * RBK + ekh);
                    pf0 = src[0]; pf1 = src[1]; pf2 = src[2]; pf3 = src[3];
                }
                const float* zs = sm_z + (s * RBK) * RBM + ty * 8;
                const float* es = sm_e + tx * 8;
#pragma unroll 8
                for (int kk = 0; kk < RBK; kk++) {
                    float4 a0 = *(const float4*)(zs + kk * RBM);
                    float4 a1 = *(const float4*)(zs + kk * RBM + 4);
                    float4 b0 = *(const float4*)(es + kk * RBN);
                    float4 b1 = *(const float4*)(es + kk * RBN + 4);
                    ull bb0, bb1, bb2, bb3;
                    PACK2(bb0, b0.x, b0.y); PACK2(bb1, b0.z, b0.w);
                    PACK2(bb2, b1.x, b1.y); PACK2(bb3, b1.z, b1.w);
                    float av[8] = {a0.x, a0.y, a0.z, a0.w, a1.x, a1.y, a1.z, a1.w};
#pragma unroll
                    for (int i = 0; i < 8; i++) {
                        ull aa; PACK2(aa, av[i], av[i]);
                        FMA2(acc2[i][0], aa, bb0);
                        FMA2(acc2[i][1], aa, bb1);
                        FMA2(acc2[i][2], aa, bb2);
                        FMA2(acc2[i][3], aa, bb3);
                    }
                }
            }

            float4 se0 = *(const float4*)(se + nbase + tx * 8);
            float4 se1 = *(const float4*)(se + nbase + tx * 8 + 4);
            float sen[8] = {se0.x, se0.y, se0.z, se0.w, se1.x, se1.y, se1.z, se1.w};
#pragma unroll
            for (int i = 0; i < 8; i++) {
                float bdv = FLT_MAX; int bnv = 0;
#pragma unroll
                for (int j2 = 0; j2 < 4; j2++) {
                    unsigned plo_u, phi_u;
                    UNPACK2(plo_u, phi_u, acc2[i][j2]);
                    float plo = __uint_as_float(plo_u);
                    float phi = __uint_as_float(phi_u);
                    float t0 = __fadd_rn(szr[i], sen[2 * j2]);
                    float t1 = __fadd_rn(szr[i], sen[2 * j2 + 1]);
                    float dd0 = __fadd_rn(t0, __fmul_rn(-2.0f, plo));
                    float dd1 = __fadd_rn(t1, __fmul_rn(-2.0f, phi));
                    if (dd0 < bdv) { bdv = dd0; bnv = nbase + tx * 8 + 2 * j2; }
                    if (dd1 < bdv) { bdv = dd1; bnv = nbase + tx * 8 + 2 * j2 + 1; }
                }
#pragma unroll
                for (int off = 8; off; off >>= 1) {
                    float od = __shfl_down_sync(0xffffffffu, bdv, off, 16);
                    int   on = __shfl_down_sync(0xffffffffu, bnv, off, 16);
                    if (od < bdv || (od == bdv && on < bnv)) { bdv = od; bnv = on; }
                }
                if (tx == 0) {
                    int rr = ty * 8 + i;
                    if (bdv < run_d[rr]) { run_d[rr] = bdv; run_n[rr] = bnv; }
                }
            }
        }

        __syncthreads();
        if (tid < RBM) {
            int li = grp * RBM + tid;
            if (li < cnt) {
                ull key = ((ull)__float_as_uint(run_d[tid]) << 32) | (unsigned)run_n[tid];
                atomicMin(&g_rmin[g_list[li]], key);
            }
        }
        __syncthreads();
    }
}

// ---------------- output gather ----------------
__global__ void gather_kernel(const float* __restrict__ emb, float* __restrict__ outp,
                              int B, int mode, long long idx_off)
{
    int w = (int)((blockIdx.x * blockDim.x + threadIdx.x) >> 5);
    int lane = threadIdx.x & 31;
    if (w >= B) return;
    int idx = g_flag[w] ? (int)(unsigned)(g_rmin[w] & 0xFFFFFFFFull) : g_idx[w];
    if (mode & 1) {
        const float4* src = (const float4*)(emb + (size_t)idx * DIM);
        float4* dst = (float4*)(outp + (size_t)w * DIM);
        dst[lane] = src[lane];
        dst[lane + 32] = src[lane + 32];
    }
    if ((mode & 2) && lane == 0) outp[idx_off + w] = (float)idx;
}

extern "C" void kernel_launch(void* const* d_in, const int* in_sizes, int n_in,
                              void* d_out, int out_size) {
    const float* z   = (const float*)d_in[0];
    const float* emb = (const float*)d_in[1];
    float* outp = (float*)d_out;

    int B  = in_sizes[0] / DIM;
    int NE = in_sizes[1] / DIM;

    float *sz_p, *se_p;
    __nv_bfloat16 *ehi_p, *elo_p;
    cudaGetSymbolAddress((void**)&sz_p,  g_sz);
    cudaGetSymbolAddress((void**)&se_p,  g_se);
    cudaGetSymbolAddress((void**)&ehi_p, g_ehi);
    cudaGetSymbolAddress((void**)&elo_p, g_elo);

    row_sumsq_kernel<<<(B + 7) / 8, 256>>>(z, sz_p, B);
    row_sumsq_kernel<<<(NE + 7) / 8, 256>>>(emb, se_p, NE);
    int ne8 = NE * DIM / 8;
    split_bf16_kernel<<<(ne8 + 255) / 256, 256>>>(emb, ehi_p, elo_p, ne8);

    init_kernel<<<(B + 255) / 256, 256>>>(B);

    int nrow = B / TM;    // 256
    cudaFuncSetAttribute(vq_mma_kernel, cudaFuncAttributeMaxDynamicSharedMemorySize, SMEM_REQ);
    vq_mma_kernel<<<nrow * NSLICE, THREADS, SMEM_REQ>>>(z, ehi_p, elo_p, sz_p, se_p, NE, nrow);

    flag_compact_kernel<<<(B + 255) / 256, 256>>>(B);

    size_t rs_smem = (size_t)(DIM * RBM + RBK * RBN + RBM) * sizeof(float) + RBM * sizeof(int);
    cudaFuncSetAttribute(rescue3_kernel, cudaFuncAttributeMaxDynamicSharedMemorySize, (int)rs_smem);
    rescue3_kernel<<<1024, 256, rs_smem>>>(z, emb, sz_p, se_p, NE);

    long long zq_elems = (long long)B * DIM;
    int mode; long long idx_off;
    if ((long long)out_size >= zq_elems + B) { mode = 3; idx_off = zq_elems; }
    else if ((long long)out_size >= zq_elems) { mode = 1; idx_off = 0; }
    else { mode = 2; idx_off = 0; }

    gather_kernel<<<(B * 32 + 255) / 256, 256>>>(emb, outp, B, mode, idx_off);
}

// round 11
// speedup vs baseline: 4.0730x; 1.0116x over previous
#include <cuda_runtime.h>
#include <cuda_bf16.h>
#include <cstdint>
#include <cfloat>

// IBQ VQ: bf16 3-term mma.sync screening (TM=64, 2 CTAs/SM, N-sliced) +
// soundness certification + fine-grained exact-fp32 tiled rescue.
//   d[b,n] = (sz[b]+se[n]) - 2*dot(z[b],e[n]);  idx=argmin (first index on ties)
// Ground truth (empirically == reference, R5-R10): sequential-k fp32 FMA chain,
// d = fadd(fadd(sz,se), fmul(-2,p)). Screening flags rows whose winner could differ;
// flagged rows are recomputed exactly; all merges via atomicMin on (d_bits,n) keys.

#define DIM      256
#define TM       64
#define TN       128
#define NSTAGE   3
#define THREADS  256
#define MAX_B    32768
#define MAX_NE   8192
#define THR      5e-7f
#define WINDOW   1.125f
#define NSLICE   4

__device__ float g_sz[MAX_B];
__device__ float g_se[MAX_NE];
__device__ __align__(16) __nv_bfloat16 g_ehi[MAX_NE * DIM];
__device__ __align__(16) __nv_bfloat16 g_elo[MAX_NE * DIM];
__device__ int   g_idx[MAX_B];
__device__ int   g_flag[MAX_B];
__device__ int   g_list[MAX_B];
__device__ int   g_cnt;
__device__ unsigned long long g_smin[MAX_B];   // screening winner key
__device__ unsigned int      g_dnm[MAX_B];     // min d over midpoint-near candidates
__device__ unsigned long long g_rmin[MAX_B];   // rescue winner key

// ---- screening smem layout (112.5 KB -> 2 CTAs/SM) ----
#define OFF_A_HI   0               // 64 rows x 512B = 32KB
#define OFF_A_LO   32768           // 32KB
#define OFF_B      65536           // 3 x 16KB
#define B_STG      16384
#define OFF_SE     114688          // 128 floats
#define SMEM_REQ   115200

__device__ __forceinline__ uint32_t smem_u32(const void* p) {
    uint32_t a;
    asm("{ .reg .u64 t; cvta.to.shared.u64 t, %1; cvt.u32.u64 %0, t; }" : "=r"(a) : "l"(p));
    return a;
}
__device__ __forceinline__ void cp16(uint32_t s, const void* g) {
    asm volatile("cp.async.cg.shared.global [%0], [%1], 16;" :: "r"(s), "l"(g));
}
#define CP_COMMIT() asm volatile("cp.async.commit_group;" ::: "memory")
#define CP_WAIT2()  asm volatile("cp.async.wait_group 2;" ::: "memory")
#define CP_WAIT0()  asm volatile("cp.async.wait_group 0;" ::: "memory")

#define LDSM4(r, a) \
    asm volatile("ldmatrix.sync.aligned.m8n8.x4.shared.b16 {%0,%1,%2,%3}, [%4];" \
                 : "=r"((r)[0]), "=r"((r)[1]), "=r"((r)[2]), "=r"((r)[3]) : "r"(a))

#define MMAB(d, a, b0, b1) \
    asm volatile("mma.sync.aligned.m16n8k16.row.col.f32.bf16.bf16.f32 " \
                 "{%0,%1,%2,%3}, {%4,%5,%6,%7}, {%8,%9}, {%0,%1,%2,%3};" \
                 : "+f"((d)[0]), "+f"((d)[1]), "+f"((d)[2]), "+f"((d)[3]) \
                 : "r"((a)[0]), "r"((a)[1]), "r"((a)[2]), "r"((a)[3]), "r"(b0), "r"(b1))

__device__ __forceinline__ uint32_t swzA(int row, int g) {   // 512B rows, g in 0..31
    return (uint32_t)(row * 512 + ((g ^ (row & 7)) << 4));
}
__device__ __forceinline__ uint32_t swzB(int row, int g) {   // 128B rows, g in 0..7
    return (uint32_t)(row * 128 + ((g ^ (row & 7)) << 4));
}
__device__ __forceinline__ float ulp_of(float d) {
    return __uint_as_float(__float_as_uint(d) & 0xFF800000u) * 1.1920929e-7f;
}
__device__ __forceinline__ void splitpair(float x, float y, uint32_t& hi, uint32_t& lo) {
    __nv_bfloat16 xh = __float2bfloat16(x), yh = __float2bfloat16(y);
    __nv_bfloat16 xl = __float2bfloat16(x - __bfloat162float(xh));
    __nv_bfloat16 yl = __float2bfloat16(y - __bfloat162float(yh));
    hi = (uint32_t)__bfloat16_as_ushort(xh) | ((uint32_t)__bfloat16_as_ushort(yh) << 16);
    lo = (uint32_t)__bfloat16_as_ushort(xl) | ((uint32_t)__bfloat16_as_ushort(yl) << 16);
}

typedef unsigned long long ull;
#define PACK2(d, x, y) \
    asm("mov.b64 %0, {%1, %2};" : "=l"(d) : "r"(__float_as_uint(x)), "r"(__float_as_uint(y)))
#define FMA2(acc, a, b) \
    asm("fma.rn.f32x2 %0, %1, %2, %3;" : "=l"(acc) : "l"(a), "l"(b), "l"(acc))
#define UNPACK2(x, y, d) \
    asm("mov.b64 {%0, %1}, %2;" : "=r"(x), "=r"(y) : "l"(d))

// ---------------- prep kernels ----------------
__global__ void row_sumsq_kernel(const float* __restrict__ x, float* __restrict__ o, int rows) {
    int w = (int)((blockIdx.x * blockDim.x + threadIdx.x) >> 5);
    int lane = threadIdx.x & 31;
    if (w >= rows) return;
    const float4* r = (const float4*)(x + (size_t)w * DIM);
    float4 v0 = r[lane * 2];
    float4 v1 = r[lane * 2 + 1];
    float s = v0.x * v0.x;
    s += v0.y * v0.y; s += v0.z * v0.z; s += v0.w * v0.w;
    s += v1.x * v1.x; s += v1.y * v1.y; s += v1.z * v1.z; s += v1.w * v1.w;
#pragma unroll
    for (int off = 16; off; off >>= 1) s += __shfl_xor_sync(0xffffffffu, s, off);
    if (lane == 0) o[w] = s;
}

__global__ void split_bf16_kernel(const float* __restrict__ x, __nv_bfloat16* __restrict__ hi,
                                  __nv_bfloat16* __restrict__ lo, int n8) {
    int i = blockIdx.x * blockDim.x + threadIdx.x;
    if (i >= n8) return;
    float4 v0 = ((const float4*)x)[i * 2];
    float4 v1 = ((const float4*)x)[i * 2 + 1];
    uint4 h, l;
    splitpair(v0.x, v0.y, h.x, l.x);
    splitpair(v0.z, v0.w, h.y, l.y);
    splitpair(v1.x, v1.y, h.z, l.z);
    splitpair(v1.z, v1.w, h.w, l.w);
    ((uint4*)hi)[i] = h;
    ((uint4*)lo)[i] = l;
}

__global__ void init_kernel(int B) {
    int i = blockIdx.x * blockDim.x + threadIdx.x;
    if (i < B) { g_smin[i] = ~0ull; g_rmin[i] = ~0ull; g_dnm[i] = 0xFFFFFFFFu; }
    if (i == 0) g_cnt = 0;
}

// ---------------- pass 1: bf16 3-term MMA + certification (TM=64, N-sliced) ----------------
__global__ void __launch_bounds__(THREADS, 2)
vq_mma_kernel(const float* __restrict__ z,
              const __nv_bfloat16* __restrict__ ehi, const __nv_bfloat16* __restrict__ elo,
              const float* __restrict__ sz, const float* __restrict__ se, int NE, int nrow)
{
    extern __shared__ char sp[];
    const uint32_t sb = smem_u32(sp);

    const int tid  = threadIdx.x;
    const int lane = tid & 31;
    const int wid  = tid >> 5;
    const int wm   = (wid & 1) * 32;              // 2 M-warp groups
    const int wn   = (wid >> 1) * 32;             // 4 N-warp groups
    // slice-major: wave CTAs share the same B slice range across row tiles
    const int rowblk = blockIdx.x % nrow;
    const int slice  = blockIdx.x / nrow;
    const int bbase  = rowblk * TM;
    const int NE_SL  = NE / NSLICE;               // 2048
    const int t0     = slice * (NE_SL / TN);
    const int NCHK   = (NE_SL / TN) * 8;          // 128 k-chunks

    const int lrowA = lane & 15;
    const int gselA = lane >> 4;
    const int lrowB = (lane & 7) + ((lane >> 4) << 3);
    const int gselB = (lane >> 3) & 1;

    float d1[4] = {FLT_MAX, FLT_MAX, FLT_MAX, FLT_MAX};
    int   n1[4] = {0, 0, 0, 0};
    float dnm[4] = {FLT_MAX, FLT_MAX, FLT_MAX, FLT_MAX};

    float szr[4];
#pragma unroll
    for (int s = 0; s < 4; s++)
        szr[s] = __ldg(sz + bbase + wm + (s >> 1) * 16 + (s & 1) * 8 + (lane >> 2));

    float acc[2][4][4];
#pragma unroll
    for (int mt = 0; mt < 2; mt++)
#pragma unroll
        for (int nt = 0; nt < 4; nt++)
#pragma unroll
            for (int k = 0; k < 4; k++) acc[mt][nt][k] = 0.0f;

    auto issue_chunk = [&](int i, int stage) {
        int c = i & 7, t = t0 + (i >> 3);
        uint32_t sB = sb + OFF_B + stage * B_STG;
        const __nv_bfloat16* gh = ehi + (size_t)(t * TN) * DIM + c * 32;
        const __nv_bfloat16* gl = elo + (size_t)(t * TN) * DIM + c * 32;
#pragma unroll
        for (int it = 0; it < 4; it++) {
            int idx = tid + it * 256;
            int row = idx >> 3, g = idx & 7;
            const void* src = (g < 4) ? (const void*)(gh + (size_t)row * DIM + g * 8)
                                      : (const void*)(gl + (size_t)row * DIM + (g - 4) * 8);
            cp16(sB + swzB(row, g), src);
        }
        CP_COMMIT();
    };

    issue_chunk(0, 0);
    issue_chunk(1, 1);
    issue_chunk(2, 2);

    // ---- persistent A fill: 64 rows, each thread handles a 64-k quarter of one row ----
    {
        int r = tid >> 2, q4 = tid & 3;
        const float4* zrow = (const float4*)(z + (size_t)(bbase + r) * DIM + q4 * 64);
#pragma unroll 2
        for (int q = 0; q < 8; q++) {
            float4 v0 = zrow[q * 2], v1 = zrow[q * 2 + 1];
            uint4 h, l;
            splitpair(v0.x, v0.y, h.x, l.x);
            splitpair(v0.z, v0.w, h.y, l.y);
            splitpair(v1.x, v1.y, h.z, l.z);
            splitpair(v1.z, v1.w, h.w, l.w);
            uint32_t off = swzA(r, q4 * 8 + q);
            *(uint4*)(sp + OFF_A_HI + off) = h;
            *(uint4*)(sp + OFF_A_LO + off) = l;
        }
    }

    float* sm_se = (float*)(sp + OFF_SE);

#pragma unroll 1
    for (int i = 0; i < NCHK; i++) {
        int stage = i % NSTAGE;
        CP_WAIT2();
        __syncthreads();      // also covers A-fill readiness on i==0

        if ((i & 7) == 0 && tid < 32)
            ((float4*)sm_se)[tid] = ((const float4*)(se + (t0 + (i >> 3)) * TN))[tid];

        uint32_t sB = sb + OFF_B + stage * B_STG;
#pragma unroll
        for (int ksl = 0; ksl < 2; ksl++) {
            int ksg = ((i & 7) << 1) | ksl;
            uint32_t ah[2][4], al[2][4], bh[2][4], bl[2][4];
#pragma unroll
            for (int mt = 0; mt < 2; mt++) {
                int row = wm + mt * 16 + lrowA;
                uint32_t ad = sb + OFF_A_HI + swzA(row, ksg * 2 + gselA);
                LDSM4(ah[mt], ad);
                LDSM4(al[mt], ad + 32768);
            }
#pragma unroll
            for (int p = 0; p < 2; p++) {
                int row = wn + p * 16 + lrowB;
                LDSM4(bh[p], sB + swzB(row, ksl * 2 + gselB));
                LDSM4(bl[p], sB + swzB(row, 4 + ksl * 2 + gselB));
            }
#pragma unroll
            for (int mt = 0; mt < 2; mt++)
#pragma unroll
                for (int nt = 0; nt < 4; nt++) {
                    int p = nt >> 1, o = (nt & 1) * 2;
                    MMAB(acc[mt][nt], ah[mt], bh[p][o], bh[p][o + 1]);
                    MMAB(acc[mt][nt], al[mt], bh[p][o], bh[p][o + 1]);
                    MMAB(acc[mt][nt], ah[mt], bl[p][o], bl[p][o + 1]);
                }
        }

        if ((i & 7) == 7) {
            int t = t0 + (i >> 3);
#pragma unroll
            for (int mt = 0; mt < 2; mt++)
#pragma unroll
                for (int half = 0; half < 2; half++) {
                    int slot = mt * 2 + half;
                    float szv = szr[slot];
#pragma unroll
                    for (int nt = 0; nt < 4; nt++)
#pragma unroll
                        for (int j = 0; j < 2; j++) {
                            float p = acc[mt][nt][half * 2 + j];
                            int nl = wn + nt * 8 + (lane & 3) * 2 + j;
                            float tt = __fadd_rn(szv, sm_se[nl]);
                            float q  = __fmul_rn(-2.0f, p);
                            float d  = __fadd_rn(tt, q);
                            float zzv = __fadd_rn(d, -tt);   // exact (Fast2Sum)
                            float r   = __fadd_rn(q, -zzv);  // exact rounding residual
                            bool nm = fabsf(r) >= (0.5f * ulp_of(d) - THR);
                            if (nm && d < dnm[slot]) dnm[slot] = d;
                            int ng = t * TN + nl;
                            if (d < d1[slot]) { d1[slot] = d; n1[slot] = ng; }
                        }
                }
#pragma unroll
            for (int mt = 0; mt < 2; mt++)
#pragma unroll
                for (int nt = 0; nt < 4; nt++)
#pragma unroll
                    for (int k = 0; k < 4; k++) acc[mt][nt][k] = 0.0f;
        }

        __syncthreads();
        if (i + NSTAGE < NCHK) issue_chunk(i + NSTAGE, stage);
    }
    CP_WAIT0();

    // quad-lane merge, then every warp atomically merges its rows (exact lexicographic)
#pragma unroll
    for (int s = 0; s < 4; s++) {
#pragma unroll
        for (int off = 1; off <= 2; off <<= 1) {
            float od = __shfl_xor_sync(0xffffffffu, d1[s], off);
            int   on = __shfl_xor_sync(0xffffffffu, n1[s], off);
            float om = __shfl_xor_sync(0xffffffffu, dnm[s], off);
            if (od < d1[s] || (od == d1[s] && on < n1[s])) { d1[s] = od; n1[s] = on; }
            if (om < dnm[s]) dnm[s] = om;
        }
    }
    if ((lane & 3) == 0) {
#pragma unroll
        for (int s = 0; s < 4; s++) {
            int row = wm + (s >> 1) * 16 + (s & 1) * 8 + (lane >> 2);
            ull key = ((ull)__float_as_uint(d1[s]) << 32) | (unsigned)n1[s];
            atomicMin(&g_smin[bbase + row], key);
            if (dnm[s] < FLT_MAX)
                atomicMin(&g_dnm[bbase + row], __float_as_uint(dnm[s]));
        }
    }
}

// ---------------- flag decision + compaction ----------------
__global__ void flag_compact_kernel(int B) {
    int i = blockIdx.x * blockDim.x + threadIdx.x;
    if (i >= B) return;
    ull key = g_smin[i];
    float d1 = __uint_as_float((unsigned)(key >> 32));
    float dm = __uint_as_float(g_dnm[i]);
    g_idx[i] = (int)(unsigned)(key & 0xFFFFFFFFull);
    int fl = (dm <= d1 + WINDOW * ulp_of(d1)) ? 1 : 0;
    g_flag[i] = fl;
    if (fl) {
        int p = atomicAdd(&g_cnt, 1);
        g_list[p] = i;
    }
}

// ---------------- rescue: exact ground-truth numerics, fine-grained (R10) ----------------
#define RBM 128
#define RBN 128
#define RBK 32
#define SLICE_N 256

__global__ void __launch_bounds__(256, 1)
rescue3_kernel(const float* __restrict__ z, const float* __restrict__ emb,
               const float* __restrict__ sz, const float* __restrict__ se, int NE)
{
    extern __shared__ float smem[];
    float* sm_z  = smem;
    float* sm_e  = smem + DIM * RBM;
    float* run_d = sm_e + RBK * RBN;
    int*   run_n = (int*)(run_d + RBM);

    const int tid = threadIdx.x;
    const int tx = tid & 15;
    const int ty = tid >> 4;
    const int cnt = g_cnt;
    const int ngrp = (cnt + RBM - 1) / RBM;
    const int nslice = NE / SLICE_N;
    const int nitems = ngrp * nslice;

    for (int item = blockIdx.x; item < nitems; item += gridDim.x) {
        const int grp = item / nslice;
        const int slice = item - grp * nslice;
        const int n0 = slice * SLICE_N;

        {
            int r = tid >> 1, half = tid & 1;
            int li = grp * RBM + r;
            int grow = g_list[li < cnt ? li : cnt - 1];
            const float4* src = (const float4*)(z + (size_t)grow * DIM + half * 128);
#pragma unroll
            for (int qq = 0; qq < 32; qq++) {
                float4 v = src[qq];
                int k = half * 128 + qq * 4;
                sm_z[(k + 0) * RBM + r] = v.x;
                sm_z[(k + 1) * RBM + r] = v.y;
                sm_z[(k + 2) * RBM + r] = v.z;
                sm_z[(k + 3) * RBM + r] = v.w;
            }
        }
        if (tid < RBM) { run_d[tid] = FLT_MAX; run_n[tid] = 0; }

        float szr[8];
#pragma unroll
        for (int i = 0; i < 8; i++) {
            int li = grp * RBM + ty * 8 + i;
            szr[i] = __ldg(sz + g_list[li < cnt ? li : cnt - 1]);
        }
        __syncthreads();

        const int ec = tid >> 1;
        const int ekh = (tid & 1) * 16;

#pragma unroll 1
        for (int nbase = n0; nbase < n0 + SLICE_N; nbase += RBN) {
            ull acc2[8][4];
#pragma unroll
            for (int i = 0; i < 8; i++)
#pragma unroll
                for (int j = 0; j < 4; j++) acc2[i][j] = 0ull;

            float4 pf0, pf1, pf2, pf3;
            {
                const float4* src = (const float4*)(emb + (size_t)(nbase + ec) * DIM + ekh);
                pf0 = src[0]; pf1 = src[1]; pf2 = src[2]; pf3 = src[3];
            }

#pragma unroll 1
            for (int s = 0; s < DIM / RBK; s++) {
                __syncthreads();
                {
                    float* dst = sm_e + ec;
                    dst[(ekh + 0)  * RBN] = pf0.x; dst[(ekh + 1)  * RBN] = pf0.y;
                    dst[(ekh + 2)  * RBN] = pf0.z; dst[(ekh + 3)  * RBN] = pf0.w;
                    dst[(ekh + 4)  * RBN] = pf1.x; dst[(ekh + 5)  * RBN] = pf1.y;
                    dst[(ekh + 6)  * RBN] = pf1.z; dst[(ekh + 7)  * RBN] = pf1.w;
                    dst[(ekh + 8)  * RBN] = pf2.x; dst[(ekh + 9)  * RBN] = pf2.y;
                    dst[(ekh + 10) * RBN] = pf2.z; dst[(ekh + 11) * RBN] = pf2.w;
                    dst[(ekh + 12) * RBN] = pf3.x; dst[(ekh + 13) * RBN] = pf3.y;
                    dst[(ekh + 14) * RBN] = pf3.z; dst[(ekh + 15) * RBN] = pf3.w;
                }
                __syncthreads();
                if (s + 1 < DIM / RBK) {
                    const float4* src = (const float4*)(emb + (size_t)(nbase + ec) * DIM
                                                        + (s + 1) * RBK + ekh);
                    pf0 = src[0]; pf1 = src[1]; pf2 = src[2]; pf3 = src[3];
                }
                const float* zs = sm_z + (s * RBK) * RBM + ty * 8;
                const float* es = sm_e + tx * 8;
#pragma unroll 8
                for (int kk = 0; kk < RBK; kk++) {
                    float4 a0 = *(const float4*)(zs + kk * RBM);
                    float4 a1 = *(const float4*)(zs + kk * RBM + 4);
                    float4 b0 = *(const float4*)(es + kk * RBN);
                    float4 b1 = *(const float4*)(es + kk * RBN + 4);
                    ull bb0, bb1, bb2, bb3;
                    PACK2(bb0, b0.x, b0.y); PACK2(bb1, b0.z, b0.w);
                    PACK2(bb2, b1.x, b1.y); PACK2(bb3, b1.z, b1.w);
                    float av[8] = {a0.x, a0.y, a0.z, a0.w, a1.x, a1.y, a1.z, a1.w};
#pragma unroll
                    for (int i = 0; i < 8; i++) {
                        ull aa; PACK2(aa, av[i], av[i]);
                        FMA2(acc2[i][0], aa, bb0);
                        FMA2(acc2[i][1], aa, bb1);
                        FMA2(acc2[i][2], aa, bb2);
                        FMA2(acc2[i][3], aa, bb3);
                    }
                }
            }

            float4 se0 = *(const float4*)(se + nbase + tx * 8);
            float4 se1 = *(const float4*)(se + nbase + tx * 8 + 4);
            float sen[8] = {se0.x, se0.y, se0.z, se0.w, se1.x, se1.y, se1.z, se1.w};
#pragma unroll
            for (int i = 0; i < 8; i++) {
                float bdv = FLT_MAX; int bnv = 0;
#pragma unroll
                for (int j2 = 0; j2 < 4; j2++) {
                    unsigned plo_u, phi_u;
                    UNPACK2(plo_u, phi_u, acc2[i][j2]);
                    float plo = __uint_as_float(plo_u);
                    float phi = __uint_as_float(phi_u);
                    float t0 = __fadd_rn(szr[i], sen[2 * j2]);
                    float t1 = __fadd_rn(szr[i], sen[2 * j2 + 1]);
                    float dd0 = __fadd_rn(t0, __fmul_rn(-2.0f, plo));
                    float dd1 = __fadd_rn(t1, __fmul_rn(-2.0f, phi));
                    if (dd0 < bdv) { bdv = dd0; bnv = nbase + tx * 8 + 2 * j2; }
                    if (dd1 < bdv) { bdv = dd1; bnv = nbase + tx * 8 + 2 * j2 + 1; }
                }
#pragma unroll
                for (int off = 8; off; off >>= 1) {
                    float od = __shfl_down_sync(0xffffffffu, bdv, off, 16);
                    int   on = __shfl_down_sync(0xffffffffu, bnv, off, 16);
                    if (od < bdv || (od == bdv && on < bnv)) { bdv = od; bnv = on; }
                }
                if (tx == 0) {
                    int rr = ty * 8 + i;
                    if (bdv < run_d[rr]) { run_d[rr] = bdv; run_n[rr] = bnv; }
                }
            }
        }

        __syncthreads();
        if (tid < RBM) {
            int li = grp * RBM + tid;
            if (li < cnt) {
                ull key = ((ull)__float_as_uint(run_d[tid]) << 32) | (unsigned)run_n[tid];
                atomicMin(&g_rmin[g_list[li]], key);
            }
        }
        __syncthreads();
    }
}

// ---------------- output gather ----------------
__global__ void gather_kernel(const float* __restrict__ emb, float* __restrict__ outp,
                              int B, int mode, long long idx_off)
{
    int w = (int)((blockIdx.x * blockDim.x + threadIdx.x) >> 5);
    int lane = threadIdx.x & 31;
    if (w >= B) return;
    int idx = g_flag[w] ? (int)(unsigned)(g_rmin[w] & 0xFFFFFFFFull) : g_idx[w];
    if (mode & 1) {
        const float4* src = (const float4*)(emb + (size_t)idx * DIM);
        float4* dst = (float4*)(outp + (size_t)w * DIM);
        dst[lane] = src[lane];
        dst[lane + 32] = src[lane + 32];
    }
    if ((mode & 2) && lane == 0) outp[idx_off + w] = (float)idx;
}

extern "C" void kernel_launch(void* const* d_in, const int* in_sizes, int n_in,
                              void* d_out, int out_size) {
    const float* z   = (const float*)d_in[0];
    const float* emb = (const float*)d_in[1];
    float* outp = (float*)d_out;

    int B  = in_sizes[0] / DIM;
    int NE = in_sizes[1] / DIM;

    float *sz_p, *se_p;
    __nv_bfloat16 *ehi_p, *elo_p;
    cudaGetSymbolAddress((void**)&sz_p,  g_sz);
    cudaGetSymbolAddress((void**)&se_p,  g_se);
    cudaGetSymbolAddress((void**)&ehi_p, g_ehi);
    cudaGetSymbolAddress((void**)&elo_p, g_elo);

    row_sumsq_kernel<<<(B + 7) / 8, 256>>>(z, sz_p, B);
    row_sumsq_kernel<<<(NE + 7) / 8, 256>>>(emb, se_p, NE);
    int ne8 = NE * DIM / 8;
    split_bf16_kernel<<<(ne8 + 255) / 256, 256>>>(emb, ehi_p, elo_p, ne8);

    init_kernel<<<(B + 255) / 256, 256>>>(B);

    int nrow = B / TM;    // 512
    cudaFuncSetAttribute(vq_mma_kernel, cudaFuncAttributeMaxDynamicSharedMemorySize, SMEM_REQ);
    vq_mma_kernel<<<nrow * NSLICE, THREADS, SMEM_REQ>>>(z, ehi_p, elo_p, sz_p, se_p, NE, nrow);

    flag_compact_kernel<<<(B + 255) / 256, 256>>>(B);

    size_t rs_smem = (size_t)(DIM * RBM + RBK * RBN + RBM) * sizeof(float) + RBM * sizeof(int);
    cudaFuncSetAttribute(rescue3_kernel, cudaFuncAttributeMaxDynamicSharedMemorySize, (int)rs_smem);
    rescue3_kernel<<<1024, 256, rs_smem>>>(z, emb, sz_p, se_p, NE);

    long long zq_elems = (long long)B * DIM;
    int mode; long long idx_off;
    if ((long long)out_size >= zq_elems + B) { mode = 3; idx_off = zq_elems; }
    else if ((long long)out_size >= zq_elems) { mode = 1; idx_off = 0; }
    else { mode = 2; idx_off = 0; }

    gather_kernel<<<(B * 32 + 255) / 256, 256>>>(emb, outp, B, mode, idx_off);
}